// round 11
// baseline (speedup 1.0000x reference)
#include <cuda_runtime.h>
#include <cuda_bf16.h>
#include <math.h>
#include <stdint.h>

#define NB 2
#define CH 128
#define NP 256
#define SS 240
#define MM 20
#define KXN 40
#define NPIX (SS*SS)
#define NPOS (NB*NPIX)
#define LSTRIDE 136   // padded row length in bf16 (272 bytes): conflict-free ldmatrix

// ---- scratch (device globals; no allocation allowed) ----
__device__ float  g_hA[NB*CH*NP*NP];
__device__ float  g_hB[NB*CH*NP*NP];
__device__ float2 g_Gy [NB*CH*NP*MM];
__device__ float2 g_Fm [NB*CH*KXN*MM];
__device__ float2 g_Fo [NB*CH*KXN*MM];
__device__ float2 g_Gy2[NB*CH*NP*MM];
__device__ float  g_feat[NPOS*CH];
__device__ float2 g_csy [NP*MM];     // (cos,sin)(2*pi*ky*y/256), y-major
__device__ float2 g_csx [NP*KXN];    // (cos,sin)(2*pi*kx*x/256), x-major
__device__ float2 g_csyT[MM*NP];     // ky-major copy

__device__ __forceinline__ float gelu_f(float v){
    return 0.5f*v*(1.0f+erff(v*0.70710678118654752f));
}

// ================= warp-mma helpers (sm_80-era PTX, legal at compute_103) =====
__device__ __forceinline__ uint32_t smem_u32(const void* p){
    uint32_t a;
    asm("{ .reg .u64 t; cvta.to.shared.u64 t, %1; cvt.u32.u64 %0, t; }" : "=r"(a) : "l"(p));
    return a;
}
__device__ __forceinline__ void ldmx4(uint32_t* r, uint32_t addr){
    asm volatile("ldmatrix.sync.aligned.m8n8.x4.shared.b16 {%0,%1,%2,%3}, [%4];"
        : "=r"(r[0]),"=r"(r[1]),"=r"(r[2]),"=r"(r[3]) : "r"(addr));
}
__device__ __forceinline__ void ldmx2t(uint32_t* r, uint32_t addr){
    asm volatile("ldmatrix.sync.aligned.m8n8.x2.trans.shared.b16 {%0,%1}, [%2];"
        : "=r"(r[0]),"=r"(r[1]) : "r"(addr));
}
__device__ __forceinline__ void mma_bf16(float* c, const uint32_t* a, const uint32_t* b){
    asm volatile("mma.sync.aligned.m16n8k16.row.col.f32.bf16.bf16.f32 "
        "{%0,%1,%2,%3}, {%4,%5,%6,%7}, {%8,%9}, {%0,%1,%2,%3};"
        : "+f"(c[0]),"+f"(c[1]),"+f"(c[2]),"+f"(c[3])
        : "r"(a[0]),"r"(a[1]),"r"(a[2]),"r"(a[3]), "r"(b[0]),"r"(b[1]));
}

// ---- twiddle tables (exact: sincospif of integer/128) ----
__global__ void k_tables(){
    int i = blockIdx.x*blockDim.x + threadIdx.x;
    if (i < NP*MM){
        int y=i/MM, ky=i%MM; float s,c;
        sincospif((float)(ky*y)*(1.0f/128.0f), &s, &c);
        g_csy[i]=make_float2(c,s);
    } else if (i < NP*MM + NP*KXN){
        int j=i-NP*MM; int xx=j/KXN, kxi=j%KXN;
        int kx = (kxi<MM)? kxi : 236+(kxi-MM);
        float s,c; sincospif((float)(kx*xx)*(1.0f/128.0f), &s, &c);
        g_csx[j]=make_float2(c,s);
    } else if (i < 2*NP*MM + NP*KXN){
        int j=i-(NP*MM+NP*KXN); int ky=j/NP, y=j%NP;
        float s,c; sincospif((float)(ky*y)*(1.0f/128.0f), &s, &c);
        g_csyT[j]=make_float2(c,s);
    }
}

// ---- fc0 + grid channels, write padded (b,c,x,y) into g_hA ----
__global__ void k_fc0(const float* __restrict__ x, const float* __restrict__ w,
                      const float* __restrict__ b){
    __shared__ float ws[5][CH];
    __shared__ float bs[CH];
    int t=threadIdx.x;
    for(int i=t;i<5*CH;i+=256) ws[i/CH][i%CH]=w[i];
    for(int i=t;i<CH;i+=256) bs[i]=b[i];
    __syncthreads();
    int xr=blockIdx.x, bb=blockIdx.y, y=t;
    bool inside=(xr<SS)&&(y<SS);
    float v0=0.f,v1=0.f,v2=0.f,v3=0.f,v4=0.f;
    if(inside){
        const float* xp=x+(((size_t)bb*SS+xr)*SS+y)*3;
        v0=xp[0]; v1=xp[1]; v2=xp[2];
        v3=(float)xr*(1.0f/239.0f);
        v4=(float)y *(1.0f/239.0f);
    }
    float* op=g_hA+(((size_t)bb*CH)*NP+xr)*NP+y;
    for(int c=0;c<CH;c++){
        float a=0.f;
        if(inside){
            a=bs[c];
            a=fmaf(v0,ws[0][c],a); a=fmaf(v1,ws[1][c],a); a=fmaf(v2,ws[2][c],a);
            a=fmaf(v3,ws[3][c],a); a=fmaf(v4,ws[4][c],a);
        }
        op[(size_t)c*NP*NP]=a;
    }
}

// ---- forward y-DFT: h(row,y) -> Gy(row,ky) ----
__global__ void __launch_bounds__(320) k_dfty(int pp){
    __shared__ float hs[32*NP];
    const float* h = pp ? g_hB : g_hA;
    int t=threadIdx.x;
    size_t rowbase=(size_t)blockIdx.x*32;
    const float* hp=h+rowbase*NP;
    for(int i=t;i<32*NP;i+=320) hs[i]=hp[i];
    __syncthreads();
    int ky=t%MM, rl=t/MM;
    const float* h0=hs+(2*rl)*NP;
    const float* h1=h0+NP;
    float a0r=0.f,a0i=0.f,a1r=0.f,a1i=0.f;
    #pragma unroll 4
    for(int y=0;y<NP;y++){
        float2 w=g_csy[y*MM+ky];
        float u0=h0[y], u1=h1[y];
        a0r=fmaf(u0,w.x,a0r); a0i=fmaf(u0,w.y,a0i);
        a1r=fmaf(u1,w.x,a1r); a1i=fmaf(u1,w.y,a1i);
    }
    g_Gy[(rowbase+2*rl  )*MM+ky]=make_float2(a0r,-a0i);
    g_Gy[(rowbase+2*rl+1)*MM+ky]=make_float2(a1r,-a1i);
}

// ---- forward x-DFT: Gy(x,ky) -> Fm(kxi,ky), one (b,c) per block ----
__global__ void __launch_bounds__(800) k_dftx(){
    __shared__ float2 gsh[NP*MM];
    int bc=blockIdx.x, t=threadIdx.x;
    const float2* gp=g_Gy+(size_t)bc*NP*MM;
    for(int i=t;i<NP*MM;i+=800) gsh[i]=gp[i];
    __syncthreads();
    int kxi=t%KXN, ky=t/KXN;
    float ar=0.f, ai=0.f;
    #pragma unroll 4
    for(int xx=0;xx<NP;xx++){
        float2 w=g_csx[xx*KXN+kxi];
        float2 f=gsh[xx*MM+ky];
        ar += f.x*w.x + f.y*w.y;
        ai += f.y*w.x - f.x*w.y;
    }
    g_Fm[((size_t)bc*KXN+kxi)*MM+ky]=make_float2(ar,ai);
}

// ---- mode mixing: Fo[b,o,p] = sum_i Fm[b,i,p]*W[i,o,p] ----
__global__ void __launch_bounds__(1024) k_mix(const float* __restrict__ w1,
                                              const float* __restrict__ w2, int l){
    __shared__ float2 fsh[2][CH][4];
    int kxi=blockIdx.x, myg=blockIdx.y, t=threadIdx.x;
    {
        int b=t>>9, rem=t&511, i=rem>>2, myl=rem&3;
        fsh[b][i][myl]=g_Fm[(((size_t)(b*CH+i))*KXN+kxi)*MM + myg*4+myl];
    }
    __syncthreads();
    int myl=t&3, b=(t>>2)&1, o=t>>3;
    int my=myg*4+myl;
    int mx=(kxi<MM)? kxi : (kxi-MM);
    const float2* wp=(const float2*)((kxi<MM)? w1 : w2);
    size_t base=(((size_t)l*CH*CH + o)*MM + mx)*MM + my;
    float ar=0.f, ai=0.f;
    #pragma unroll 4
    for(int i=0;i<CH;i++){
        float2 wv=wp[base+(size_t)i*CH*MM*MM];
        float2 f=fsh[b][i][myl];
        ar += f.x*wv.x - f.y*wv.y;
        ai += f.x*wv.y + f.y*wv.x;
    }
    g_Fo[(((size_t)(b*CH+o))*KXN+kxi)*MM+my]=make_float2(ar,ai);
}

// ---- inverse x-DFT: Fo(kxi,ky) -> Gy2(x,ky), pre-scaled ----
__global__ void __launch_bounds__(512) k_idftx(){
    __shared__ float2 fsh[KXN*MM];
    int bo=blockIdx.x, t=threadIdx.x;
    const float2* fp=g_Fo+(size_t)bo*KXN*MM;
    for(int i=t;i<KXN*MM;i+=512) fsh[i]=fp[i];
    __syncthreads();
    int xx=t&255, kg=t>>8;
    float ar[10], ai[10];
    #pragma unroll
    for(int j=0;j<10;j++){ ar[j]=0.f; ai[j]=0.f; }
    for(int k=0;k<KXN;k++){
        float2 w=g_csx[xx*KXN+k];
        #pragma unroll
        for(int j=0;j<10;j++){
            float2 f=fsh[k*MM+kg*10+j];
            ar[j] += f.x*w.x - f.y*w.y;
            ai[j] += f.x*w.y + f.y*w.x;
        }
    }
    float2* op=g_Gy2+((size_t)bo*NP+xx)*MM;
    #pragma unroll
    for(int j=0;j<10;j++){
        int ky=kg*10+j;
        float fk=((ky==0)?1.0f:2.0f)*(1.0f/65536.0f);
        op[ky]=make_float2(ar[j]*fk, ai[j]*fk);
    }
}

// ---- inverse y-DFT (real part): write spectral term s into dst ----
__global__ void __launch_bounds__(256) k_idfty(int pp){
    __shared__ float2 rsh[32*MM];
    float* dst = pp ? g_hA : g_hB;
    int t=threadIdx.x;
    size_t rowbase=(size_t)blockIdx.x*32;
    const float2* gp=g_Gy2+rowbase*MM;
    for(int i=t;i<32*MM;i+=256) rsh[i]=gp[i];
    float cy[MM], sy[MM];
    #pragma unroll
    for(int ky=0;ky<MM;ky++){ float2 w=g_csyT[ky*NP+t]; cy[ky]=w.x; sy[ky]=w.y; }
    __syncthreads();
    for(int r=0;r<32;r++){
        float a=0.f;
        #pragma unroll
        for(int ky=0;ky<MM;ky++){
            float2 f=rsh[r*MM+ky];
            a=fmaf(f.x,cy[ky],a);
            a=fmaf(-f.y,sy[ky],a);
        }
        dst[(rowbase+r)*NP+t]=a;
    }
}

// ---- 1x1 conv via mma.sync bf16 split (3-pass) + spectral + bias (+gelu) ----
// grid (512,1,NB), 256 threads = 8 warps (2 M x 4 N); tile M=128(o) N=128(y) K=128(c)
__global__ void __launch_bounds__(256) k_lin_mma(int pp, const float* __restrict__ ww,
                                                 const float* __restrict__ wb, int l, int dogelu){
    extern __shared__ __nv_bfloat16 sm[];
    __nv_bfloat16* Ahi = sm;                     // W  [o][c], row pad LSTRIDE
    __nv_bfloat16* Alo = Ahi + 128*LSTRIDE;
    __nv_bfloat16* Bhi = Alo + 128*LSTRIDE;      // h  [c][y] (K x N row-major)
    __nv_bfloat16* Blo = Bhi + 128*LSTRIDE;
    const float* src = pp ? g_hB : g_hA;
    float*       dst = pp ? g_hA : g_hB;
    int t=threadIdx.x, lane=t&31, wid=t>>5;
    int x=blockIdx.x>>1, ybase=(blockIdx.x&1)<<7, bb=blockIdx.z;
    const float* W = ww + (size_t)l*CH*CH;

    // stage A = W split
    #pragma unroll 4
    for(int i=0;i<16;i++){
        int idx=i*256+t; int o=idx>>5, c4=(idx&31)*4;
        float4 w4=*(const float4*)(W+(size_t)o*CH+c4);
        float vv[4]={w4.x,w4.y,w4.z,w4.w};
        #pragma unroll
        for(int j=0;j<4;j++){
            __nv_bfloat16 hi=__float2bfloat16(vv[j]);
            __nv_bfloat16 lo=__float2bfloat16(vv[j]-__bfloat162float(hi));
            Ahi[o*LSTRIDE+c4+j]=hi; Alo[o*LSTRIDE+c4+j]=lo;
        }
    }
    // stage B = h split (already K-major in gmem: [c][y])
    const float* srow = src + (((size_t)bb*CH)*NP + x)*NP + ybase;
    #pragma unroll 4
    for(int i=0;i<16;i++){
        int idx=i*256+t; int c=idx>>5, y4=(idx&31)*4;
        float4 h4=*(const float4*)(srow+(size_t)c*NP*NP+y4);
        float vv[4]={h4.x,h4.y,h4.z,h4.w};
        #pragma unroll
        for(int j=0;j<4;j++){
            __nv_bfloat16 hi=__float2bfloat16(vv[j]);
            __nv_bfloat16 lo=__float2bfloat16(vv[j]-__bfloat162float(hi));
            Bhi[c*LSTRIDE+y4+j]=hi; Blo[c*LSTRIDE+y4+j]=lo;
        }
    }
    __syncthreads();

    int wm=(wid>>2)*64, wn=(wid&3)*32;
    float acc[4][4][4];
    #pragma unroll
    for(int mi=0;mi<4;mi++)
        #pragma unroll
        for(int ni=0;ni<4;ni++)
            #pragma unroll
            for(int q=0;q<4;q++) acc[mi][ni][q]=0.f;

    uint32_t AhiB=smem_u32(Ahi), AloB=smem_u32(Alo);
    uint32_t BhiB=smem_u32(Bhi), BloB=smem_u32(Blo);
    int arow=lane&15;
    uint32_t acolb=(uint32_t)((lane>>4)<<4);

    for(int kk=0;kk<8;kk++){
        uint32_t a[4][4];
        #pragma unroll
        for(int mi=0;mi<4;mi++){
            uint32_t off=(uint32_t)((wm+mi*16+arow)*(2*LSTRIDE) + kk*32) + acolb;
            ldmx4(a[mi], AhiB+off);
        }
        uint32_t bh[4][2], bl[4][2];
        #pragma unroll
        for(int ni=0;ni<4;ni++){
            uint32_t off=(uint32_t)((kk*16+arow)*(2*LSTRIDE) + (wn+ni*8)*2);
            ldmx2t(bh[ni], BhiB+off);
            ldmx2t(bl[ni], BloB+off);
        }
        #pragma unroll
        for(int mi=0;mi<4;mi++)
            #pragma unroll
            for(int ni=0;ni<4;ni++){
                mma_bf16(acc[mi][ni], a[mi], bh[ni]);
                mma_bf16(acc[mi][ni], a[mi], bl[ni]);
            }
        #pragma unroll
        for(int mi=0;mi<4;mi++){
            uint32_t off=(uint32_t)((wm+mi*16+arow)*(2*LSTRIDE) + kk*32) + acolb;
            ldmx4(a[mi], AloB+off);
        }
        #pragma unroll
        for(int mi=0;mi<4;mi++)
            #pragma unroll
            for(int ni=0;ni<4;ni++)
                mma_bf16(acc[mi][ni], a[mi], bh[ni]);
    }

    // epilogue: D + spectral(dst) + bias (+gelu), float2 RMW
    int r0=lane>>2, c0=(lane&3)*2;
    #pragma unroll
    for(int mi=0;mi<4;mi++){
        int o0=wm+mi*16+r0, o1=o0+8;
        float bias0=__ldg(wb+l*CH+o0), bias1=__ldg(wb+l*CH+o1);
        float* base0=dst+(((size_t)(bb*CH+o0))*NP+x)*NP+ybase;
        float* base1=dst+(((size_t)(bb*CH+o1))*NP+x)*NP+ybase;
        #pragma unroll
        for(int ni=0;ni<4;ni++){
            int y=wn+ni*8+c0;
            float2* p0=(float2*)(base0+y);
            float2 v0=*p0;
            v0.x+=acc[mi][ni][0]+bias0; v0.y+=acc[mi][ni][1]+bias0;
            if(dogelu){ v0.x=gelu_f(v0.x); v0.y=gelu_f(v0.y); }
            *p0=v0;
            float2* p1=(float2*)(base1+y);
            float2 v1=*p1;
            v1.x+=acc[mi][ni][2]+bias1; v1.y+=acc[mi][ni][3]+bias1;
            if(dogelu){ v1.x=gelu_f(v1.x); v1.y=gelu_f(v1.y); }
            *p1=v1;
        }
    }
}

// ---- crop + fc1 + gelu -> g_feat (p-major, c contiguous) ----
__global__ void __launch_bounds__(256) k_fc1(const float* __restrict__ w,
                                             const float* __restrict__ b){
    __shared__ float As[16][64];
    __shared__ float Bs[16][64];
    int t=threadIdx.x;
    int pbase=blockIdx.x*64, obase=blockIdx.y<<6;
    int lo=t&63, kq=t>>6;
    int p=pbase+lo;
    int bb=p/NPIX; int rem=p-bb*NPIX;
    int xr=rem/SS;  int yr=rem-xr*SS;
    size_t base=(size_t)bb*CH*NP*NP + (size_t)xr*NP + yr;
    float acc[4][4];
    #pragma unroll
    for(int i=0;i<4;i++){ acc[i][0]=0.f; acc[i][1]=0.f; acc[i][2]=0.f; acc[i][3]=0.f; }
    int tp=t&15, to=t>>4;
    for(int c0=0;c0<CH;c0+=16){
        #pragma unroll
        for(int q=0;q<4;q++){
            int kk=kq*4+q;
            As[kk][lo]=w[(size_t)(c0+kk)*CH + obase+lo];
            Bs[kk][lo]=g_hB[base + (size_t)(c0+kk)*NP*NP];
        }
        __syncthreads();
        #pragma unroll
        for(int kk=0;kk<16;kk++){
            float4 a =*(const float4*)&As[kk][to*4];
            float4 bv=*(const float4*)&Bs[kk][tp*4];
            float av[4]={a.x,a.y,a.z,a.w};
            float bvv[4]={bv.x,bv.y,bv.z,bv.w};
            #pragma unroll
            for(int pi=0;pi<4;pi++)
                #pragma unroll
                for(int oj=0;oj<4;oj++)
                    acc[pi][oj]=fmaf(bvv[pi],av[oj],acc[pi][oj]);
        }
        __syncthreads();
    }
    #pragma unroll
    for(int pi=0;pi<4;pi++){
        float* fp=g_feat+(size_t)(pbase+tp*4+pi)*CH + obase+to*4;
        float4 o4;
        o4.x=gelu_f(acc[pi][0]+b[obase+to*4+0]);
        o4.y=gelu_f(acc[pi][1]+b[obase+to*4+1]);
        o4.z=gelu_f(acc[pi][2]+b[obase+to*4+2]);
        o4.w=gelu_f(acc[pi][3]+b[obase+to*4+3]);
        *(float4*)fp=o4;
    }
}

// ---- 4 heads: gelu(feat@W1k+b1)@W2k + b2 -> out ----
__global__ void __launch_bounds__(256) k_heads(const float* __restrict__ w1,
                                               const float* __restrict__ b1,
                                               const float* __restrict__ w2,
                                               const float* __restrict__ b2,
                                               float* __restrict__ out){
    __shared__ float Fs[32][65];
    __shared__ float Ws[32][64];
    __shared__ float red[64][17];
    int t=threadIdx.x;
    int pbase=blockIdx.x*64;
    int tp=t&15, td=t>>4;
    for(int k=0;k<4;k++){
        float acc[4][4];
        #pragma unroll
        for(int i=0;i<4;i++){ acc[i][0]=0.f; acc[i][1]=0.f; acc[i][2]=0.f; acc[i][3]=0.f; }
        for(int c0=0;c0<CH;c0+=32){
            for(int i=t;i<2048;i+=256){
                int r=i>>6, cc=i&63;
                Ws[r][cc]=w1[(size_t)k*CH*64 + (size_t)(c0+r)*64 + cc];
            }
            for(int i=t;i<2048;i+=256){
                int c=i&31, pl=i>>5;
                Fs[c][pl]=g_feat[(size_t)(pbase+pl)*CH + c0 + c];
            }
            __syncthreads();
            #pragma unroll 8
            for(int kk=0;kk<32;kk++){
                float4 a=*(const float4*)&Ws[kk][td*4];
                float av[4]={a.x,a.y,a.z,a.w};
                float f0=Fs[kk][tp*4+0], f1=Fs[kk][tp*4+1];
                float f2=Fs[kk][tp*4+2], f3=Fs[kk][tp*4+3];
                #pragma unroll
                for(int dj=0;dj<4;dj++){
                    acc[0][dj]=fmaf(f0,av[dj],acc[0][dj]);
                    acc[1][dj]=fmaf(f1,av[dj],acc[1][dj]);
                    acc[2][dj]=fmaf(f2,av[dj],acc[2][dj]);
                    acc[3][dj]=fmaf(f3,av[dj],acc[3][dj]);
                }
            }
            __syncthreads();
        }
        #pragma unroll
        for(int pi=0;pi<4;pi++){
            float v=0.f;
            #pragma unroll
            for(int dj=0;dj<4;dj++){
                int d=td*4+dj;
                float h1=gelu_f(acc[pi][dj]+b1[k*64+d]);
                v=fmaf(h1, w2[k*64+d], v);
            }
            red[tp*4+pi][td]=v;
        }
        __syncthreads();
        if(t<64){
            float v=b2[k];
            #pragma unroll
            for(int j=0;j<16;j++) v+=red[t][j];
            out[(size_t)k*NPOS + pbase + t]=v;
        }
        __syncthreads();
    }
}

extern "C" void kernel_launch(void* const* d_in, const int* in_sizes, int n_in,
                              void* d_out, int out_size){
    (void)in_sizes; (void)n_in; (void)out_size;
    const float* x     =(const float*)d_in[0];
    const float* fc0_w =(const float*)d_in[1];
    const float* fc0_b =(const float*)d_in[2];
    const float* sw1   =(const float*)d_in[3];
    const float* sw2   =(const float*)d_in[4];
    const float* w_w   =(const float*)d_in[5];
    const float* w_b   =(const float*)d_in[6];
    const float* fc1_w =(const float*)d_in[7];
    const float* fc1_b =(const float*)d_in[8];
    const float* h1w   =(const float*)d_in[9];
    const float* h1b   =(const float*)d_in[10];
    const float* h2w   =(const float*)d_in[11];
    const float* h2b   =(const float*)d_in[12];
    float* out=(float*)d_out;

    const int LIN_SMEM = 4*128*LSTRIDE*2;   // 139264 bytes
    cudaFuncSetAttribute(k_lin_mma, cudaFuncAttributeMaxDynamicSharedMemorySize, LIN_SMEM);

    k_tables<<<80,256>>>();
    k_fc0<<<dim3(NP,NB),256>>>(x,fc0_w,fc0_b);
    for(int l=0;l<5;l++){
        int pp=l&1;
        k_dfty <<<NB*CH*NP/32,320>>>(pp);
        k_dftx <<<NB*CH,800>>>();
        k_mix  <<<dim3(KXN,5),1024>>>(sw1,sw2,l);
        k_idftx<<<NB*CH,512>>>();
        k_idfty<<<NB*CH*NP/32,256>>>(pp);
        k_lin_mma<<<dim3(512,1,NB),256,LIN_SMEM>>>(pp,w_w,w_b,l,(l<4)?1:0);
    }
    k_fc1  <<<dim3(NPOS/64,2),256>>>(fc1_w,fc1_b);
    k_heads<<<NPOS/64,256>>>(h1w,h1b,h2w,h2b,out);
}

// round 12
// speedup vs baseline: 1.1853x; 1.1853x over previous
#include <cuda_runtime.h>
#include <cuda_bf16.h>
#include <math.h>
#include <stdint.h>

#define NB 2
#define CH 128
#define NP 256
#define SS 240
#define MM 20
#define KXN 40
#define NPIX (SS*SS)
#define NPOS (NB*NPIX)
#define ASTR 72    // A smem row stride in bf16 (144B = 9*16B)
#define BSTR 136   // B smem row stride in bf16 (272B = 17*16B)

// ---- scratch (device globals; no allocation allowed) ----
__device__ float  g_hA[NB*CH*NP*NP];
__device__ float  g_hB[NB*CH*NP*NP];
__device__ float2 g_Gy [NB*CH*NP*MM];
__device__ float2 g_Fm [NB*CH*KXN*MM];
__device__ float2 g_Fo [NB*CH*KXN*MM];
__device__ float2 g_Gy2[NB*CH*NP*MM];
__device__ float  g_feat[NPOS*CH];
__device__ float2 g_csy [NP*MM];     // (cos,sin)(2*pi*ky*y/256), y-major
__device__ float2 g_csx [NP*KXN];    // (cos,sin)(2*pi*kx*x/256), x-major
__device__ float2 g_csyT[MM*NP];     // ky-major copy

__device__ __forceinline__ float gelu_f(float v){
    return 0.5f*v*(1.0f+erff(v*0.70710678118654752f));
}

// ================= warp-mma helpers =================
__device__ __forceinline__ uint32_t smem_u32(const void* p){
    uint32_t a;
    asm("{ .reg .u64 t; cvta.to.shared.u64 t, %1; cvt.u32.u64 %0, t; }" : "=r"(a) : "l"(p));
    return a;
}
__device__ __forceinline__ void ldmx4(uint32_t* r, uint32_t addr){
    asm volatile("ldmatrix.sync.aligned.m8n8.x4.shared.b16 {%0,%1,%2,%3}, [%4];"
        : "=r"(r[0]),"=r"(r[1]),"=r"(r[2]),"=r"(r[3]) : "r"(addr));
}
__device__ __forceinline__ void ldmx2t(uint32_t* r, uint32_t addr){
    asm volatile("ldmatrix.sync.aligned.m8n8.x2.trans.shared.b16 {%0,%1}, [%2];"
        : "=r"(r[0]),"=r"(r[1]) : "r"(addr));
}
__device__ __forceinline__ void mma_bf16(float* c, const uint32_t* a, const uint32_t* b){
    asm volatile("mma.sync.aligned.m16n8k16.row.col.f32.bf16.bf16.f32 "
        "{%0,%1,%2,%3}, {%4,%5,%6,%7}, {%8,%9}, {%0,%1,%2,%3};"
        : "+f"(c[0]),"+f"(c[1]),"+f"(c[2]),"+f"(c[3])
        : "r"(a[0]),"r"(a[1]),"r"(a[2]),"r"(a[3]), "r"(b[0]),"r"(b[1]));
}
// pack (lo,hi) floats -> bf16x2 with rn rounding
__device__ __forceinline__ uint32_t pkbf2(float lo, float hi){
    uint32_t r; asm("cvt.rn.bf16x2.f32 %0, %1, %2;" : "=r"(r) : "f"(hi), "f"(lo)); return r;
}

// ---- twiddle tables (exact: sincospif of integer/128) ----
__global__ void k_tables(){
    int i = blockIdx.x*blockDim.x + threadIdx.x;
    if (i < NP*MM){
        int y=i/MM, ky=i%MM; float s,c;
        sincospif((float)(ky*y)*(1.0f/128.0f), &s, &c);
        g_csy[i]=make_float2(c,s);
    } else if (i < NP*MM + NP*KXN){
        int j=i-NP*MM; int xx=j/KXN, kxi=j%KXN;
        int kx = (kxi<MM)? kxi : 236+(kxi-MM);
        float s,c; sincospif((float)(kx*xx)*(1.0f/128.0f), &s, &c);
        g_csx[j]=make_float2(c,s);
    } else if (i < 2*NP*MM + NP*KXN){
        int j=i-(NP*MM+NP*KXN); int ky=j/NP, y=j%NP;
        float s,c; sincospif((float)(ky*y)*(1.0f/128.0f), &s, &c);
        g_csyT[j]=make_float2(c,s);
    }
}

// ---- fc0 + grid channels, write padded (b,c,x,y) into g_hA ----
__global__ void k_fc0(const float* __restrict__ x, const float* __restrict__ w,
                      const float* __restrict__ b){
    __shared__ float ws[5][CH];
    __shared__ float bs[CH];
    int t=threadIdx.x;
    for(int i=t;i<5*CH;i+=256) ws[i/CH][i%CH]=w[i];
    for(int i=t;i<CH;i+=256) bs[i]=b[i];
    __syncthreads();
    int xr=blockIdx.x, bb=blockIdx.y, y=t;
    bool inside=(xr<SS)&&(y<SS);
    float v0=0.f,v1=0.f,v2=0.f,v3=0.f,v4=0.f;
    if(inside){
        const float* xp=x+(((size_t)bb*SS+xr)*SS+y)*3;
        v0=xp[0]; v1=xp[1]; v2=xp[2];
        v3=(float)xr*(1.0f/239.0f);
        v4=(float)y *(1.0f/239.0f);
    }
    float* op=g_hA+(((size_t)bb*CH)*NP+xr)*NP+y;
    for(int c=0;c<CH;c++){
        float a=0.f;
        if(inside){
            a=bs[c];
            a=fmaf(v0,ws[0][c],a); a=fmaf(v1,ws[1][c],a); a=fmaf(v2,ws[2][c],a);
            a=fmaf(v3,ws[3][c],a); a=fmaf(v4,ws[4][c],a);
        }
        op[(size_t)c*NP*NP]=a;
    }
}

// ---- forward y-DFT: h(row,y) -> Gy(row,ky), 32 rows/block, 4 rows/thread ----
__global__ void __launch_bounds__(160) k_dfty(int pp){
    __shared__ float hs[32*NP];
    const float* h = pp ? g_hB : g_hA;
    int t=threadIdx.x;
    size_t rowbase=(size_t)blockIdx.x*32;
    const float* hp=h+rowbase*NP;
    for(int i=t;i<32*NP;i+=160) hs[i]=hp[i];
    __syncthreads();
    int ky=t%MM, rl=t/MM;                 // rl 0..7, 4 rows each
    const float* h0=hs+(4*rl)*NP;
    const float* h1=h0+NP;
    const float* h2=h1+NP;
    const float* h3=h2+NP;
    float a0r=0.f,a0i=0.f,a1r=0.f,a1i=0.f;
    float a2r=0.f,a2i=0.f,a3r=0.f,a3i=0.f;
    #pragma unroll 4
    for(int y=0;y<NP;y++){
        float2 w=g_csy[y*MM+ky];
        float u0=h0[y], u1=h1[y], u2=h2[y], u3=h3[y];
        a0r=fmaf(u0,w.x,a0r); a0i=fmaf(u0,w.y,a0i);
        a1r=fmaf(u1,w.x,a1r); a1i=fmaf(u1,w.y,a1i);
        a2r=fmaf(u2,w.x,a2r); a2i=fmaf(u2,w.y,a2i);
        a3r=fmaf(u3,w.x,a3r); a3i=fmaf(u3,w.y,a3i);
    }
    g_Gy[(rowbase+4*rl  )*MM+ky]=make_float2(a0r,-a0i);
    g_Gy[(rowbase+4*rl+1)*MM+ky]=make_float2(a1r,-a1i);
    g_Gy[(rowbase+4*rl+2)*MM+ky]=make_float2(a2r,-a2i);
    g_Gy[(rowbase+4*rl+3)*MM+ky]=make_float2(a3r,-a3i);
}

// ---- forward x-DFT: Gy(x,ky) -> Fm(kxi,ky), one (b,c) per block ----
__global__ void __launch_bounds__(800) k_dftx(){
    __shared__ float2 gsh[NP*MM];
    int bc=blockIdx.x, t=threadIdx.x;
    const float2* gp=g_Gy+(size_t)bc*NP*MM;
    for(int i=t;i<NP*MM;i+=800) gsh[i]=gp[i];
    __syncthreads();
    int kxi=t%KXN, ky=t/KXN;
    float ar=0.f, ai=0.f;
    #pragma unroll 4
    for(int xx=0;xx<NP;xx++){
        float2 w=g_csx[xx*KXN+kxi];
        float2 f=gsh[xx*MM+ky];
        ar += f.x*w.x + f.y*w.y;
        ai += f.y*w.x - f.x*w.y;
    }
    g_Fm[((size_t)bc*KXN+kxi)*MM+ky]=make_float2(ar,ai);
}

// ---- mode mixing: Fo[b,o,p] = sum_i Fm[b,i,p]*W[i,o,p] ----
__global__ void __launch_bounds__(1024) k_mix(const float* __restrict__ w1,
                                              const float* __restrict__ w2, int l){
    __shared__ float2 fsh[2][CH][4];
    int kxi=blockIdx.x, myg=blockIdx.y, t=threadIdx.x;
    {
        int b=t>>9, rem=t&511, i=rem>>2, myl=rem&3;
        fsh[b][i][myl]=g_Fm[(((size_t)(b*CH+i))*KXN+kxi)*MM + myg*4+myl];
    }
    __syncthreads();
    int myl=t&3, b=(t>>2)&1, o=t>>3;
    int my=myg*4+myl;
    int mx=(kxi<MM)? kxi : (kxi-MM);
    const float2* wp=(const float2*)((kxi<MM)? w1 : w2);
    size_t base=(((size_t)l*CH*CH + o)*MM + mx)*MM + my;
    float ar=0.f, ai=0.f;
    #pragma unroll 4
    for(int i=0;i<CH;i++){
        float2 wv=wp[base+(size_t)i*CH*MM*MM];
        float2 f=fsh[b][i][myl];
        ar += f.x*wv.x - f.y*wv.y;
        ai += f.x*wv.y + f.y*wv.x;
    }
    g_Fo[(((size_t)(b*CH+o))*KXN+kxi)*MM+my]=make_float2(ar,ai);
}

// ---- inverse x-DFT: Fo(kxi,ky) -> Gy2(x,ky), pre-scaled ----
__global__ void __launch_bounds__(512) k_idftx(){
    __shared__ float2 fsh[KXN*MM];
    int bo=blockIdx.x, t=threadIdx.x;
    const float2* fp=g_Fo+(size_t)bo*KXN*MM;
    for(int i=t;i<KXN*MM;i+=512) fsh[i]=fp[i];
    __syncthreads();
    int xx=t&255, kg=t>>8;
    float ar[10], ai[10];
    #pragma unroll
    for(int j=0;j<10;j++){ ar[j]=0.f; ai[j]=0.f; }
    for(int k=0;k<KXN;k++){
        float2 w=g_csx[xx*KXN+k];
        #pragma unroll
        for(int j=0;j<10;j++){
            float2 f=fsh[k*MM+kg*10+j];
            ar[j] += f.x*w.x - f.y*w.y;
            ai[j] += f.x*w.y + f.y*w.x;
        }
    }
    float2* op=g_Gy2+((size_t)bo*NP+xx)*MM;
    #pragma unroll
    for(int j=0;j<10;j++){
        int ky=kg*10+j;
        float fk=((ky==0)?1.0f:2.0f)*(1.0f/65536.0f);
        op[ky]=make_float2(ar[j]*fk, ai[j]*fk);
    }
}

// ---- inverse y-DFT (real part): write spectral term s into dst ----
__global__ void __launch_bounds__(256) k_idfty(int pp){
    __shared__ float2 rsh[32*MM];
    float* dst = pp ? g_hA : g_hB;
    int t=threadIdx.x;
    size_t rowbase=(size_t)blockIdx.x*32;
    const float2* gp=g_Gy2+rowbase*MM;
    for(int i=t;i<32*MM;i+=256) rsh[i]=gp[i];
    float cy[MM], sy[MM];
    #pragma unroll
    for(int ky=0;ky<MM;ky++){ float2 w=g_csyT[ky*NP+t]; cy[ky]=w.x; sy[ky]=w.y; }
    __syncthreads();
    for(int r=0;r<32;r++){
        float a=0.f;
        #pragma unroll
        for(int ky=0;ky<MM;ky++){
            float2 f=rsh[r*MM+ky];
            a=fmaf(f.x,cy[ky],a);
            a=fmaf(-f.y,sy[ky],a);
        }
        dst[(rowbase+r)*NP+t]=a;
    }
}

// ---- 1x1 conv via mma.sync bf16 split (3-pass), K-chunked, 2 CTAs/SM ----
// grid (512,1,NB), 256 threads = 8 warps (2 M x 4 N); tile M=128(o) N=128(y), K in 2x64
__global__ void __launch_bounds__(256,2) k_lin_mma(int pp, const float* __restrict__ ww,
                                                   const float* __restrict__ wb, int l, int dogelu){
    extern __shared__ __nv_bfloat16 sm[];
    __nv_bfloat16* Ahi = sm;                 // [128 o][ASTR]
    __nv_bfloat16* Alo = Ahi + 128*ASTR;
    __nv_bfloat16* Bhi = Alo + 128*ASTR;     // [64 c][BSTR]
    __nv_bfloat16* Blo = Bhi + 64*BSTR;
    const float* src = pp ? g_hB : g_hA;
    float*       dst = pp ? g_hA : g_hB;
    int t=threadIdx.x, lane=t&31, wid=t>>5;
    int x=blockIdx.x>>1, ybase=(blockIdx.x&1)<<7, bb=blockIdx.z;
    const float* W = ww + (size_t)l*CH*CH;
    const float* srow = src + (((size_t)bb*CH)*NP + x)*NP + ybase;

    int wm=(wid>>2)*64, wn=(wid&3)*32;
    float acc[4][4][4];
    #pragma unroll
    for(int mi=0;mi<4;mi++)
        #pragma unroll
        for(int ni=0;ni<4;ni++){
            acc[mi][ni][0]=0.f; acc[mi][ni][1]=0.f;
            acc[mi][ni][2]=0.f; acc[mi][ni][3]=0.f;
        }

    uint32_t AhiB=smem_u32(Ahi), AloB=smem_u32(Alo);
    uint32_t BhiB=smem_u32(Bhi), BloB=smem_u32(Blo);
    int arow=lane&15;
    uint32_t acolb=(uint32_t)((lane>>4)<<4);

    for(int kc=0;kc<2;kc++){
        // stage A chunk: W[o][kc*64 + cl], split bf16, packed 8B stores
        #pragma unroll
        for(int i=0;i<8;i++){
            int idx=i*256+t;                 // 2048 float4
            int o=idx>>4, c4=(idx&15)*4;
            float4 w4=*(const float4*)(W+(size_t)o*CH+kc*64+c4);
            uint32_t h0=pkbf2(w4.x,w4.y), h1=pkbf2(w4.z,w4.w);
            float r0=w4.x-__uint_as_float(h0<<16);
            float r1=w4.y-__uint_as_float(h0&0xFFFF0000u);
            float r2=w4.z-__uint_as_float(h1<<16);
            float r3=w4.w-__uint_as_float(h1&0xFFFF0000u);
            uint32_t l0=pkbf2(r0,r1), l1=pkbf2(r2,r3);
            *(uint2*)&Ahi[o*ASTR+c4]=make_uint2(h0,h1);
            *(uint2*)&Alo[o*ASTR+c4]=make_uint2(l0,l1);
        }
        // stage B chunk: h[kc*64 + c][y], split bf16
        #pragma unroll
        for(int i=0;i<8;i++){
            int idx=i*256+t;
            int c=idx>>5, y4=(idx&31)*4;
            float4 h4=*(const float4*)(srow+(size_t)(kc*64+c)*NP*NP+y4);
            uint32_t h0=pkbf2(h4.x,h4.y), h1=pkbf2(h4.z,h4.w);
            float r0=h4.x-__uint_as_float(h0<<16);
            float r1=h4.y-__uint_as_float(h0&0xFFFF0000u);
            float r2=h4.z-__uint_as_float(h1<<16);
            float r3=h4.w-__uint_as_float(h1&0xFFFF0000u);
            uint32_t l0=pkbf2(r0,r1), l1=pkbf2(r2,r3);
            *(uint2*)&Bhi[c*BSTR+y4]=make_uint2(h0,h1);
            *(uint2*)&Blo[c*BSTR+y4]=make_uint2(l0,l1);
        }
        __syncthreads();

        #pragma unroll
        for(int kk=0;kk<4;kk++){
            uint32_t a[4][4];
            #pragma unroll
            for(int mi=0;mi<4;mi++){
                uint32_t off=(uint32_t)((wm+mi*16+arow)*(2*ASTR) + kk*32) + acolb;
                ldmx4(a[mi], AhiB+off);
            }
            uint32_t bh[4][2], bl[4][2];
            #pragma unroll
            for(int ni=0;ni<4;ni++){
                uint32_t off=(uint32_t)((kk*16+arow)*(2*BSTR) + (wn+ni*8)*2);
                ldmx2t(bh[ni], BhiB+off);
                ldmx2t(bl[ni], BloB+off);
            }
            #pragma unroll
            for(int mi=0;mi<4;mi++)
                #pragma unroll
                for(int ni=0;ni<4;ni++){
                    mma_bf16(acc[mi][ni], a[mi], bh[ni]);
                    mma_bf16(acc[mi][ni], a[mi], bl[ni]);
                }
            #pragma unroll
            for(int mi=0;mi<4;mi++){
                uint32_t off=(uint32_t)((wm+mi*16+arow)*(2*ASTR) + kk*32) + acolb;
                ldmx4(a[mi], AloB+off);
            }
            #pragma unroll
            for(int mi=0;mi<4;mi++)
                #pragma unroll
                for(int ni=0;ni<4;ni++)
                    mma_bf16(acc[mi][ni], a[mi], bh[ni]);
        }
        __syncthreads();
    }

    // epilogue: D + spectral(dst) + bias (+gelu), float2 RMW
    int r0=lane>>2, c0=(lane&3)*2;
    #pragma unroll
    for(int mi=0;mi<4;mi++){
        int o0=wm+mi*16+r0, o1=o0+8;
        float bias0=__ldg(wb+l*CH+o0), bias1=__ldg(wb+l*CH+o1);
        float* base0=dst+(((size_t)(bb*CH+o0))*NP+x)*NP+ybase;
        float* base1=dst+(((size_t)(bb*CH+o1))*NP+x)*NP+ybase;
        #pragma unroll
        for(int ni=0;ni<4;ni++){
            int y=wn+ni*8+c0;
            float2* p0=(float2*)(base0+y);
            float2 v0=*p0;
            v0.x+=acc[mi][ni][0]+bias0; v0.y+=acc[mi][ni][1]+bias0;
            if(dogelu){ v0.x=gelu_f(v0.x); v0.y=gelu_f(v0.y); }
            *p0=v0;
            float2* p1=(float2*)(base1+y);
            float2 v1=*p1;
            v1.x+=acc[mi][ni][2]+bias1; v1.y+=acc[mi][ni][3]+bias1;
            if(dogelu){ v1.x=gelu_f(v1.x); v1.y=gelu_f(v1.y); }
            *p1=v1;
        }
    }
}

// ---- crop + fc1 + gelu -> g_feat (p-major, c contiguous) ----
__global__ void __launch_bounds__(256) k_fc1(const float* __restrict__ w,
                                             const float* __restrict__ b){
    __shared__ float As[16][64];
    __shared__ float Bs[16][64];
    int t=threadIdx.x;
    int pbase=blockIdx.x*64, obase=blockIdx.y<<6;
    int lo=t&63, kq=t>>6;
    int p=pbase+lo;
    int bb=p/NPIX; int rem=p-bb*NPIX;
    int xr=rem/SS;  int yr=rem-xr*SS;
    size_t base=(size_t)bb*CH*NP*NP + (size_t)xr*NP + yr;
    float acc[4][4];
    #pragma unroll
    for(int i=0;i<4;i++){ acc[i][0]=0.f; acc[i][1]=0.f; acc[i][2]=0.f; acc[i][3]=0.f; }
    int tp=t&15, to=t>>4;
    for(int c0=0;c0<CH;c0+=16){
        #pragma unroll
        for(int q=0;q<4;q++){
            int kk=kq*4+q;
            As[kk][lo]=w[(size_t)(c0+kk)*CH + obase+lo];
            Bs[kk][lo]=g_hB[base + (size_t)(c0+kk)*NP*NP];
        }
        __syncthreads();
        #pragma unroll
        for(int kk=0;kk<16;kk++){
            float4 a =*(const float4*)&As[kk][to*4];
            float4 bv=*(const float4*)&Bs[kk][tp*4];
            float av[4]={a.x,a.y,a.z,a.w};
            float bvv[4]={bv.x,bv.y,bv.z,bv.w};
            #pragma unroll
            for(int pi=0;pi<4;pi++)
                #pragma unroll
                for(int oj=0;oj<4;oj++)
                    acc[pi][oj]=fmaf(bvv[pi],av[oj],acc[pi][oj]);
        }
        __syncthreads();
    }
    #pragma unroll
    for(int pi=0;pi<4;pi++){
        float* fp=g_feat+(size_t)(pbase+tp*4+pi)*CH + obase+to*4;
        float4 o4;
        o4.x=gelu_f(acc[pi][0]+b[obase+to*4+0]);
        o4.y=gelu_f(acc[pi][1]+b[obase+to*4+1]);
        o4.z=gelu_f(acc[pi][2]+b[obase+to*4+2]);
        o4.w=gelu_f(acc[pi][3]+b[obase+to*4+3]);
        *(float4*)fp=o4;
    }
}

// ---- 4 heads: gelu(feat@W1k+b1)@W2k + b2 -> out ----
__global__ void __launch_bounds__(256) k_heads(const float* __restrict__ w1,
                                               const float* __restrict__ b1,
                                               const float* __restrict__ w2,
                                               const float* __restrict__ b2,
                                               float* __restrict__ out){
    __shared__ float Fs[32][65];
    __shared__ float Ws[32][64];
    __shared__ float red[64][17];
    int t=threadIdx.x;
    int pbase=blockIdx.x*64;
    int tp=t&15, td=t>>4;
    for(int k=0;k<4;k++){
        float acc[4][4];
        #pragma unroll
        for(int i=0;i<4;i++){ acc[i][0]=0.f; acc[i][1]=0.f; acc[i][2]=0.f; acc[i][3]=0.f; }
        for(int c0=0;c0<CH;c0+=32){
            for(int i=t;i<2048;i+=256){
                int r=i>>6, cc=i&63;
                Ws[r][cc]=w1[(size_t)k*CH*64 + (size_t)(c0+r)*64 + cc];
            }
            for(int i=t;i<2048;i+=256){
                int c=i&31, pl=i>>5;
                Fs[c][pl]=g_feat[(size_t)(pbase+pl)*CH + c0 + c];
            }
            __syncthreads();
            #pragma unroll 8
            for(int kk=0;kk<32;kk++){
                float4 a=*(const float4*)&Ws[kk][td*4];
                float av[4]={a.x,a.y,a.z,a.w};
                float f0=Fs[kk][tp*4+0], f1=Fs[kk][tp*4+1];
                float f2=Fs[kk][tp*4+2], f3=Fs[kk][tp*4+3];
                #pragma unroll
                for(int dj=0;dj<4;dj++){
                    acc[0][dj]=fmaf(f0,av[dj],acc[0][dj]);
                    acc[1][dj]=fmaf(f1,av[dj],acc[1][dj]);
                    acc[2][dj]=fmaf(f2,av[dj],acc[2][dj]);
                    acc[3][dj]=fmaf(f3,av[dj],acc[3][dj]);
                }
            }
            __syncthreads();
        }
        #pragma unroll
        for(int pi=0;pi<4;pi++){
            float v=0.f;
            #pragma unroll
            for(int dj=0;dj<4;dj++){
                int d=td*4+dj;
                float h1=gelu_f(acc[pi][dj]+b1[k*64+d]);
                v=fmaf(h1, w2[k*64+d], v);
            }
            red[tp*4+pi][td]=v;
        }
        __syncthreads();
        if(t<64){
            float v=b2[k];
            #pragma unroll
            for(int j=0;j<16;j++) v+=red[t][j];
            out[(size_t)k*NPOS + pbase + t]=v;
        }
        __syncthreads();
    }
}

extern "C" void kernel_launch(void* const* d_in, const int* in_sizes, int n_in,
                              void* d_out, int out_size){
    (void)in_sizes; (void)n_in; (void)out_size;
    const float* x     =(const float*)d_in[0];
    const float* fc0_w =(const float*)d_in[1];
    const float* fc0_b =(const float*)d_in[2];
    const float* sw1   =(const float*)d_in[3];
    const float* sw2   =(const float*)d_in[4];
    const float* w_w   =(const float*)d_in[5];
    const float* w_b   =(const float*)d_in[6];
    const float* fc1_w =(const float*)d_in[7];
    const float* fc1_b =(const float*)d_in[8];
    const float* h1w   =(const float*)d_in[9];
    const float* h1b   =(const float*)d_in[10];
    const float* h2w   =(const float*)d_in[11];
    const float* h2b   =(const float*)d_in[12];
    float* out=(float*)d_out;

    const int LIN_SMEM = (2*128*ASTR + 2*64*BSTR)*2;   // 71680 bytes
    cudaFuncSetAttribute(k_lin_mma, cudaFuncAttributeMaxDynamicSharedMemorySize, LIN_SMEM);

    k_tables<<<80,256>>>();
    k_fc0<<<dim3(NP,NB),256>>>(x,fc0_w,fc0_b);
    for(int l=0;l<5;l++){
        int pp=l&1;
        k_dfty <<<NB*CH*NP/32,160>>>(pp);
        k_dftx <<<NB*CH,800>>>();
        k_mix  <<<dim3(KXN,5),1024>>>(sw1,sw2,l);
        k_idftx<<<NB*CH,512>>>();
        k_idfty<<<NB*CH*NP/32,256>>>(pp);
        k_lin_mma<<<dim3(512,1,NB),256,LIN_SMEM>>>(pp,w_w,w_b,l,(l<4)?1:0);
    }
    k_fc1  <<<dim3(NPOS/64,2),256>>>(fc1_w,fc1_b);
    k_heads<<<NPOS/64,256>>>(h1w,h1b,h2w,h2b,out);
}

// round 13
// speedup vs baseline: 1.5105x; 1.2744x over previous
#include <cuda_runtime.h>
#include <cuda_bf16.h>
#include <math.h>
#include <stdint.h>

#define NB 2
#define CH 128
#define NP 256
#define SS 240
#define MM 20
#define KXN 40
#define NPIX (SS*SS)
#define NPOS (NB*NPIX)
#define ASTR 72    // k_lin A row stride (bf16)
#define BSTR 136   // k_lin B row stride (bf16)
#define DASTR 72   // dfty A stride
#define DBSTR 56   // dfty B stride
#define IASTR 56   // idfty A stride
#define IBSTR 136  // idfty B stride

// ---- scratch (device globals; no allocation allowed) ----
__device__ float  g_hA[NB*CH*NP*NP];
__device__ float  g_hB[NB*CH*NP*NP];
__device__ float2 g_Gy [NB*CH*NP*MM];
__device__ float2 g_Fm [NB*CH*KXN*MM];
__device__ float2 g_Fo [NB*CH*KXN*MM];
__device__ float2 g_Gy2[NB*CH*NP*MM];
__device__ float  g_feat[NPOS*CH];
__device__ float2 g_csx [NP*KXN];    // (cos,sin)(2*pi*kx*x/256), x-major
// split-bf16 twiddle tables for tensor DFT
__device__ __nv_bfloat16 g_Tf_hi[NP*48], g_Tf_lo[NP*48];   // dfty  B: [y][n]
__device__ __nv_bfloat16 g_Ti_hi[48*NP], g_Ti_lo[48*NP];   // idfty B: [k][y]

__device__ __forceinline__ float gelu_f(float v){
    return 0.5f*v*(1.0f+erff(v*0.70710678118654752f));
}

// ================= warp-mma helpers =================
__device__ __forceinline__ uint32_t smem_u32(const void* p){
    uint32_t a;
    asm("{ .reg .u64 t; cvta.to.shared.u64 t, %1; cvt.u32.u64 %0, t; }" : "=r"(a) : "l"(p));
    return a;
}
__device__ __forceinline__ void ldmx4(uint32_t* r, uint32_t addr){
    asm volatile("ldmatrix.sync.aligned.m8n8.x4.shared.b16 {%0,%1,%2,%3}, [%4];"
        : "=r"(r[0]),"=r"(r[1]),"=r"(r[2]),"=r"(r[3]) : "r"(addr));
}
__device__ __forceinline__ void ldmx2t(uint32_t* r, uint32_t addr){
    asm volatile("ldmatrix.sync.aligned.m8n8.x2.trans.shared.b16 {%0,%1}, [%2];"
        : "=r"(r[0]),"=r"(r[1]) : "r"(addr));
}
__device__ __forceinline__ void mma_bf16(float* c, const uint32_t* a, const uint32_t* b){
    asm volatile("mma.sync.aligned.m16n8k16.row.col.f32.bf16.bf16.f32 "
        "{%0,%1,%2,%3}, {%4,%5,%6,%7}, {%8,%9}, {%0,%1,%2,%3};"
        : "+f"(c[0]),"+f"(c[1]),"+f"(c[2]),"+f"(c[3])
        : "r"(a[0]),"r"(a[1]),"r"(a[2]),"r"(a[3]), "r"(b[0]),"r"(b[1]));
}
__device__ __forceinline__ uint32_t pkbf2(float lo, float hi){
    uint32_t r; asm("cvt.rn.bf16x2.f32 %0, %1, %2;" : "=r"(r) : "f"(hi), "f"(lo)); return r;
}

// ---- twiddle tables ----
__global__ void k_tables(){
    int i = blockIdx.x*blockDim.x + threadIdx.x;
    if (i < NP*KXN){
        int xx=i/KXN, kxi=i%KXN;
        int kx = (kxi<MM)? kxi : 236+(kxi-MM);
        float s,c; sincospif((float)(kx*xx)*(1.0f/128.0f), &s, &c);
        g_csx[i]=make_float2(c,s);
    }
}
// split-bf16 DFT matrices: T[y][2ky]=cos, T[y][2ky+1]=-sin; Ti = T^T
__global__ void k_packtw(){
    int n=blockIdx.x, y=threadIdx.x;
    float v=0.f;
    if(n<40){
        int ky=n>>1;
        float s,c; sincospif((float)(ky*y)*(1.0f/128.0f), &s, &c);
        v = (n&1)? -s : c;
    }
    __nv_bfloat16 hi=__float2bfloat16(v);
    __nv_bfloat16 lo=__float2bfloat16(v-__bfloat162float(hi));
    g_Tf_hi[y*48+n]=hi; g_Tf_lo[y*48+n]=lo;
    g_Ti_hi[n*NP+y]=hi; g_Ti_lo[n*NP+y]=lo;
}

// ---- fc0 + grid channels, write padded (b,c,x,y) into g_hA ----
__global__ void k_fc0(const float* __restrict__ x, const float* __restrict__ w,
                      const float* __restrict__ b){
    __shared__ float ws[5][CH];
    __shared__ float bs[CH];
    int t=threadIdx.x;
    for(int i=t;i<5*CH;i+=256) ws[i/CH][i%CH]=w[i];
    for(int i=t;i<CH;i+=256) bs[i]=b[i];
    __syncthreads();
    int xr=blockIdx.x, bb=blockIdx.y, y=t;
    bool inside=(xr<SS)&&(y<SS);
    float v0=0.f,v1=0.f,v2=0.f,v3=0.f,v4=0.f;
    if(inside){
        const float* xp=x+(((size_t)bb*SS+xr)*SS+y)*3;
        v0=xp[0]; v1=xp[1]; v2=xp[2];
        v3=(float)xr*(1.0f/239.0f);
        v4=(float)y *(1.0f/239.0f);
    }
    float* op=g_hA+(((size_t)bb*CH)*NP+xr)*NP+y;
    for(int c=0;c<CH;c++){
        float a=0.f;
        if(inside){
            a=bs[c];
            a=fmaf(v0,ws[0][c],a); a=fmaf(v1,ws[1][c],a); a=fmaf(v2,ws[2][c],a);
            a=fmaf(v3,ws[3][c],a); a=fmaf(v4,ws[4][c],a);
        }
        op[(size_t)c*NP*NP]=a;
    }
}

// ---- forward y-DFT via mma: Gy[row][ky] = (sum h*cos, -sum h*sin) ----
// 512 blocks x 128 rows; 8 warps x 16 rows; N=48 (40 live), K=256 in 4x64 chunks
__global__ void __launch_bounds__(256,2) k_dfty_mma(int pp){
    extern __shared__ __nv_bfloat16 smD[];
    __nv_bfloat16* Ahi=smD;                   // [128][DASTR]
    __nv_bfloat16* Alo=Ahi+128*DASTR;
    __nv_bfloat16* Bhi=Alo+128*DASTR;         // [64][DBSTR]
    __nv_bfloat16* Blo=Bhi+64*DBSTR;
    const float* h = pp? g_hB : g_hA;
    int t=threadIdx.x, lane=t&31, wid=t>>5;
    size_t rowbase=(size_t)blockIdx.x*128;
    const float* srow = h + rowbase*NP;
    float acc[6][4];
    #pragma unroll
    for(int ni=0;ni<6;ni++){ acc[ni][0]=0.f; acc[ni][1]=0.f; acc[ni][2]=0.f; acc[ni][3]=0.f; }
    uint32_t AhiB=smem_u32(Ahi), AloB=smem_u32(Alo);
    uint32_t BhiB=smem_u32(Bhi), BloB=smem_u32(Blo);
    int arow=lane&15;
    uint32_t acolb=(uint32_t)((lane>>4)<<4);
    int wm=wid*16;

    for(int kc=0;kc<4;kc++){
        #pragma unroll
        for(int i=0;i<8;i++){                 // A: 128 rows x 64 k
            int idx=i*256+t; int r=idx>>4, c4=(idx&15)*4;
            float4 v=*(const float4*)(srow+(size_t)r*NP+kc*64+c4);
            uint32_t h0=pkbf2(v.x,v.y), h1=pkbf2(v.z,v.w);
            float r0=v.x-__uint_as_float(h0<<16);
            float r1=v.y-__uint_as_float(h0&0xFFFF0000u);
            float r2=v.z-__uint_as_float(h1<<16);
            float r3=v.w-__uint_as_float(h1&0xFFFF0000u);
            *(uint2*)&Ahi[r*DASTR+c4]=make_uint2(h0,h1);
            *(uint2*)&Alo[r*DASTR+c4]=make_uint2(pkbf2(r0,r1),pkbf2(r2,r3));
        }
        #pragma unroll
        for(int i=0;i<6;i++){                 // B: 64 k x 48 n (prepacked)
            int idx=i*256+t; int k=idx/24, n2=(idx%24)*2;
            *(uint32_t*)&Bhi[k*DBSTR+n2]=*(const uint32_t*)&g_Tf_hi[(kc*64+k)*48+n2];
            *(uint32_t*)&Blo[k*DBSTR+n2]=*(const uint32_t*)&g_Tf_lo[(kc*64+k)*48+n2];
        }
        __syncthreads();
        #pragma unroll
        for(int kk=0;kk<4;kk++){
            uint32_t a[4];
            uint32_t aoff=(uint32_t)((wm+arow)*(2*DASTR)+kk*32)+acolb;
            ldmx4(a, AhiB+aoff);
            uint32_t bh[6][2], bl[6][2];
            #pragma unroll
            for(int ni=0;ni<6;ni++){
                uint32_t off=(uint32_t)((kk*16+arow)*(2*DBSTR)+ni*16);
                ldmx2t(bh[ni], BhiB+off);
                ldmx2t(bl[ni], BloB+off);
            }
            #pragma unroll
            for(int ni=0;ni<6;ni++){
                mma_bf16(acc[ni], a, bh[ni]);
                mma_bf16(acc[ni], a, bl[ni]);
            }
            uint32_t a2[4];
            ldmx4(a2, AloB+aoff);
            #pragma unroll
            for(int ni=0;ni<6;ni++)
                mma_bf16(acc[ni], a2, bh[ni]);
        }
        __syncthreads();
    }
    int r0=lane>>2, cq=lane&3;
    #pragma unroll
    for(int ni=0;ni<5;ni++){
        int ky=ni*4+cq;
        g_Gy[(rowbase+wm+r0  )*MM+ky]=make_float2(acc[ni][0],acc[ni][1]);
        g_Gy[(rowbase+wm+r0+8)*MM+ky]=make_float2(acc[ni][2],acc[ni][3]);
    }
}

// ---- forward x-DFT: Gy(x,ky) -> Fm(kxi,ky), one (b,c) per block ----
__global__ void __launch_bounds__(800) k_dftx(){
    __shared__ float2 gsh[NP*MM];
    int bc=blockIdx.x, t=threadIdx.x;
    const float2* gp=g_Gy+(size_t)bc*NP*MM;
    for(int i=t;i<NP*MM;i+=800) gsh[i]=gp[i];
    __syncthreads();
    int kxi=t%KXN, ky=t/KXN;
    float ar=0.f, ai=0.f;
    #pragma unroll 4
    for(int xx=0;xx<NP;xx++){
        float2 w=g_csx[xx*KXN+kxi];
        float2 f=gsh[xx*MM+ky];
        ar += f.x*w.x + f.y*w.y;
        ai += f.y*w.x - f.x*w.y;
    }
    g_Fm[((size_t)bc*KXN+kxi)*MM+ky]=make_float2(ar,ai);
}

// ---- mode mixing: Fo[b,o,p] = sum_i Fm[b,i,p]*W[i,o,p] ----
__global__ void __launch_bounds__(1024) k_mix(const float* __restrict__ w1,
                                              const float* __restrict__ w2, int l){
    __shared__ float2 fsh[2][CH][4];
    int kxi=blockIdx.x, myg=blockIdx.y, t=threadIdx.x;
    {
        int b=t>>9, rem=t&511, i=rem>>2, myl=rem&3;
        fsh[b][i][myl]=g_Fm[(((size_t)(b*CH+i))*KXN+kxi)*MM + myg*4+myl];
    }
    __syncthreads();
    int myl=t&3, b=(t>>2)&1, o=t>>3;
    int my=myg*4+myl;
    int mx=(kxi<MM)? kxi : (kxi-MM);
    const float2* wp=(const float2*)((kxi<MM)? w1 : w2);
    size_t base=(((size_t)l*CH*CH + o)*MM + mx)*MM + my;
    float ar=0.f, ai=0.f;
    #pragma unroll 4
    for(int i=0;i<CH;i++){
        float2 wv=wp[base+(size_t)i*CH*MM*MM];
        float2 f=fsh[b][i][myl];
        ar += f.x*wv.x - f.y*wv.y;
        ai += f.x*wv.y + f.y*wv.x;
    }
    g_Fo[(((size_t)(b*CH+o))*KXN+kxi)*MM+my]=make_float2(ar,ai);
}

// ---- inverse x-DFT: Fo(kxi,ky) -> Gy2(x,ky), pre-scaled ----
__global__ void __launch_bounds__(512) k_idftx(){
    __shared__ float2 fsh[KXN*MM];
    int bo=blockIdx.x, t=threadIdx.x;
    const float2* fp=g_Fo+(size_t)bo*KXN*MM;
    for(int i=t;i<KXN*MM;i+=512) fsh[i]=fp[i];
    __syncthreads();
    int xx=t&255, kg=t>>8;
    float ar[10], ai[10];
    #pragma unroll
    for(int j=0;j<10;j++){ ar[j]=0.f; ai[j]=0.f; }
    for(int k=0;k<KXN;k++){
        float2 w=g_csx[xx*KXN+k];
        #pragma unroll
        for(int j=0;j<10;j++){
            float2 f=fsh[k*MM+kg*10+j];
            ar[j] += f.x*w.x - f.y*w.y;
            ai[j] += f.x*w.y + f.y*w.x;
        }
    }
    float2* op=g_Gy2+((size_t)bo*NP+xx)*MM;
    #pragma unroll
    for(int j=0;j<10;j++){
        int ky=kg*10+j;
        float fk=((ky==0)?1.0f:2.0f)*(1.0f/65536.0f);
        op[ky]=make_float2(ar[j]*fk, ai[j]*fk);
    }
}

// ---- inverse y-DFT via mma: dst[row][y] = sum_k Gy2[row][k]*Ti[k][y] ----
// grid (512, 2): 128 rows x 128 cols per block; K=48 (40 live)
__global__ void __launch_bounds__(256,2) k_idfty_mma(int pp){
    extern __shared__ __nv_bfloat16 smI[];
    __nv_bfloat16* Ahi=smI;                   // [128][IASTR]
    __nv_bfloat16* Alo=Ahi+128*IASTR;
    __nv_bfloat16* Bhi=Alo+128*IASTR;         // [48][IBSTR]
    __nv_bfloat16* Blo=Bhi+48*IBSTR;
    float* dst = pp? g_hA : g_hB;
    int t=threadIdx.x, lane=t&31, wid=t>>5;
    size_t rowbase=(size_t)blockIdx.x*128;
    int nbase=blockIdx.y*128;
    const float* arow_g=(const float*)g_Gy2 + rowbase*2*MM;

    #pragma unroll
    for(int i=0;i<5;i++){                     // A: 128 rows x 40 floats
        int idx=i*256+t; int r=idx/10, j4=(idx%10)*4;
        float4 v=*(const float4*)(arow_g+(size_t)r*40+j4);
        uint32_t h0=pkbf2(v.x,v.y), h1=pkbf2(v.z,v.w);
        float r0=v.x-__uint_as_float(h0<<16);
        float r1=v.y-__uint_as_float(h0&0xFFFF0000u);
        float r2=v.z-__uint_as_float(h1<<16);
        float r3=v.w-__uint_as_float(h1&0xFFFF0000u);
        *(uint2*)&Ahi[r*IASTR+j4]=make_uint2(h0,h1);
        *(uint2*)&Alo[r*IASTR+j4]=make_uint2(pkbf2(r0,r1),pkbf2(r2,r3));
    }
    #pragma unroll
    for(int i=0;i<4;i++){                     // zero pad k=40..47
        int idx=i*256+t; int r=idx>>3, c=idx&7;
        Ahi[r*IASTR+40+c]=__float2bfloat16(0.f);
        Alo[r*IASTR+40+c]=__float2bfloat16(0.f);
    }
    #pragma unroll
    for(int i=0;i<6;i++){                     // B: 48 k x 128 cols
        int idx=i*256+t; int k=idx>>5, n4=(idx&31)*4;
        *(uint2*)&Bhi[k*IBSTR+n4]=*(const uint2*)&g_Ti_hi[k*NP+nbase+n4];
        *(uint2*)&Blo[k*IBSTR+n4]=*(const uint2*)&g_Ti_lo[k*NP+nbase+n4];
    }
    __syncthreads();

    int wm=(wid>>2)*64, wn=(wid&3)*32;
    float acc[4][4][4];
    #pragma unroll
    for(int mi=0;mi<4;mi++)
        #pragma unroll
        for(int ni=0;ni<4;ni++){
            acc[mi][ni][0]=0.f; acc[mi][ni][1]=0.f;
            acc[mi][ni][2]=0.f; acc[mi][ni][3]=0.f;
        }
    uint32_t AhiB=smem_u32(Ahi), AloB=smem_u32(Alo);
    uint32_t BhiB=smem_u32(Bhi), BloB=smem_u32(Blo);
    int arow=lane&15;
    uint32_t acolb=(uint32_t)((lane>>4)<<4);

    #pragma unroll
    for(int kk=0;kk<3;kk++){
        uint32_t a[4][4];
        #pragma unroll
        for(int mi=0;mi<4;mi++){
            uint32_t off=(uint32_t)((wm+mi*16+arow)*(2*IASTR)+kk*32)+acolb;
            ldmx4(a[mi], AhiB+off);
        }
        uint32_t bh[4][2], bl[4][2];
        #pragma unroll
        for(int ni=0;ni<4;ni++){
            uint32_t off=(uint32_t)((kk*16+arow)*(2*IBSTR)+(wn+ni*8)*2);
            ldmx2t(bh[ni], BhiB+off);
            ldmx2t(bl[ni], BloB+off);
        }
        #pragma unroll
        for(int mi=0;mi<4;mi++)
            #pragma unroll
            for(int ni=0;ni<4;ni++){
                mma_bf16(acc[mi][ni], a[mi], bh[ni]);
                mma_bf16(acc[mi][ni], a[mi], bl[ni]);
            }
        #pragma unroll
        for(int mi=0;mi<4;mi++){
            uint32_t off=(uint32_t)((wm+mi*16+arow)*(2*IASTR)+kk*32)+acolb;
            ldmx4(a[mi], AloB+off);
        }
        #pragma unroll
        for(int mi=0;mi<4;mi++)
            #pragma unroll
            for(int ni=0;ni<4;ni++)
                mma_bf16(acc[mi][ni], a[mi], bh[ni]);
    }

    int r0=lane>>2, c0=(lane&3)*2;
    #pragma unroll
    for(int mi=0;mi<4;mi++){
        size_t row0=rowbase+wm+mi*16+r0;
        #pragma unroll
        for(int ni=0;ni<4;ni++){
            int col=nbase+wn+ni*8+c0;
            *(float2*)&dst[row0*NP+col]    =make_float2(acc[mi][ni][0],acc[mi][ni][1]);
            *(float2*)&dst[(row0+8)*NP+col]=make_float2(acc[mi][ni][2],acc[mi][ni][3]);
        }
    }
}

// ---- 1x1 conv via mma.sync bf16 split (3-pass), K-chunked, 2 CTAs/SM ----
__global__ void __launch_bounds__(256,2) k_lin_mma(int pp, const float* __restrict__ ww,
                                                   const float* __restrict__ wb, int l, int dogelu){
    extern __shared__ __nv_bfloat16 sm[];
    __nv_bfloat16* Ahi = sm;                 // [128 o][ASTR]
    __nv_bfloat16* Alo = Ahi + 128*ASTR;
    __nv_bfloat16* Bhi = Alo + 128*ASTR;     // [64 c][BSTR]
    __nv_bfloat16* Blo = Bhi + 64*BSTR;
    const float* src = pp ? g_hB : g_hA;
    float*       dst = pp ? g_hA : g_hB;
    int t=threadIdx.x, lane=t&31, wid=t>>5;
    int x=blockIdx.x>>1, ybase=(blockIdx.x&1)<<7, bb=blockIdx.z;
    const float* W = ww + (size_t)l*CH*CH;
    const float* srow = src + (((size_t)bb*CH)*NP + x)*NP + ybase;

    int wm=(wid>>2)*64, wn=(wid&3)*32;
    float acc[4][4][4];
    #pragma unroll
    for(int mi=0;mi<4;mi++)
        #pragma unroll
        for(int ni=0;ni<4;ni++){
            acc[mi][ni][0]=0.f; acc[mi][ni][1]=0.f;
            acc[mi][ni][2]=0.f; acc[mi][ni][3]=0.f;
        }
    uint32_t AhiB=smem_u32(Ahi), AloB=smem_u32(Alo);
    uint32_t BhiB=smem_u32(Bhi), BloB=smem_u32(Blo);
    int arow=lane&15;
    uint32_t acolb=(uint32_t)((lane>>4)<<4);

    for(int kc=0;kc<2;kc++){
        #pragma unroll
        for(int i=0;i<8;i++){
            int idx=i*256+t;
            int o=idx>>4, c4=(idx&15)*4;
            float4 w4=*(const float4*)(W+(size_t)o*CH+kc*64+c4);
            uint32_t h0=pkbf2(w4.x,w4.y), h1=pkbf2(w4.z,w4.w);
            float r0=w4.x-__uint_as_float(h0<<16);
            float r1=w4.y-__uint_as_float(h0&0xFFFF0000u);
            float r2=w4.z-__uint_as_float(h1<<16);
            float r3=w4.w-__uint_as_float(h1&0xFFFF0000u);
            *(uint2*)&Ahi[o*ASTR+c4]=make_uint2(h0,h1);
            *(uint2*)&Alo[o*ASTR+c4]=make_uint2(pkbf2(r0,r1),pkbf2(r2,r3));
        }
        #pragma unroll
        for(int i=0;i<8;i++){
            int idx=i*256+t;
            int c=idx>>5, y4=(idx&31)*4;
            float4 h4=*(const float4*)(srow+(size_t)(kc*64+c)*NP*NP+y4);
            uint32_t h0=pkbf2(h4.x,h4.y), h1=pkbf2(h4.z,h4.w);
            float r0=h4.x-__uint_as_float(h0<<16);
            float r1=h4.y-__uint_as_float(h0&0xFFFF0000u);
            float r2=h4.z-__uint_as_float(h1<<16);
            float r3=h4.w-__uint_as_float(h1&0xFFFF0000u);
            *(uint2*)&Bhi[c*BSTR+y4]=make_uint2(h0,h1);
            *(uint2*)&Blo[c*BSTR+y4]=make_uint2(pkbf2(r0,r1),pkbf2(r2,r3));
        }
        __syncthreads();
        #pragma unroll
        for(int kk=0;kk<4;kk++){
            uint32_t a[4][4];
            #pragma unroll
            for(int mi=0;mi<4;mi++){
                uint32_t off=(uint32_t)((wm+mi*16+arow)*(2*ASTR)+kk*32)+acolb;
                ldmx4(a[mi], AhiB+off);
            }
            uint32_t bh[4][2], bl[4][2];
            #pragma unroll
            for(int ni=0;ni<4;ni++){
                uint32_t off=(uint32_t)((kk*16+arow)*(2*BSTR)+(wn+ni*8)*2);
                ldmx2t(bh[ni], BhiB+off);
                ldmx2t(bl[ni], BloB+off);
            }
            #pragma unroll
            for(int mi=0;mi<4;mi++)
                #pragma unroll
                for(int ni=0;ni<4;ni++){
                    mma_bf16(acc[mi][ni], a[mi], bh[ni]);
                    mma_bf16(acc[mi][ni], a[mi], bl[ni]);
                }
            #pragma unroll
            for(int mi=0;mi<4;mi++){
                uint32_t off=(uint32_t)((wm+mi*16+arow)*(2*ASTR)+kk*32)+acolb;
                ldmx4(a[mi], AloB+off);
            }
            #pragma unroll
            for(int mi=0;mi<4;mi++)
                #pragma unroll
                for(int ni=0;ni<4;ni++)
                    mma_bf16(acc[mi][ni], a[mi], bh[ni]);
        }
        __syncthreads();
    }

    int r0=lane>>2, c0=(lane&3)*2;
    #pragma unroll
    for(int mi=0;mi<4;mi++){
        int o0=wm+mi*16+r0, o1=o0+8;
        float bias0=__ldg(wb+l*CH+o0), bias1=__ldg(wb+l*CH+o1);
        float* base0=dst+(((size_t)(bb*CH+o0))*NP+x)*NP+ybase;
        float* base1=dst+(((size_t)(bb*CH+o1))*NP+x)*NP+ybase;
        #pragma unroll
        for(int ni=0;ni<4;ni++){
            int y=wn+ni*8+c0;
            float2* p0=(float2*)(base0+y);
            float2 v0=*p0;
            v0.x+=acc[mi][ni][0]+bias0; v0.y+=acc[mi][ni][1]+bias0;
            if(dogelu){ v0.x=gelu_f(v0.x); v0.y=gelu_f(v0.y); }
            *p0=v0;
            float2* p1=(float2*)(base1+y);
            float2 v1=*p1;
            v1.x+=acc[mi][ni][2]+bias1; v1.y+=acc[mi][ni][3]+bias1;
            if(dogelu){ v1.x=gelu_f(v1.x); v1.y=gelu_f(v1.y); }
            *p1=v1;
        }
    }
}

// ---- crop + fc1 + gelu -> g_feat (p-major, c contiguous) ----
__global__ void __launch_bounds__(256) k_fc1(const float* __restrict__ w,
                                             const float* __restrict__ b){
    __shared__ float As[16][64];
    __shared__ float Bs[16][64];
    int t=threadIdx.x;
    int pbase=blockIdx.x*64, obase=blockIdx.y<<6;
    int lo=t&63, kq=t>>6;
    int p=pbase+lo;
    int bb=p/NPIX; int rem=p-bb*NPIX;
    int xr=rem/SS;  int yr=rem-xr*SS;
    size_t base=(size_t)bb*CH*NP*NP + (size_t)xr*NP + yr;
    float acc[4][4];
    #pragma unroll
    for(int i=0;i<4;i++){ acc[i][0]=0.f; acc[i][1]=0.f; acc[i][2]=0.f; acc[i][3]=0.f; }
    int tp=t&15, to=t>>4;
    for(int c0=0;c0<CH;c0+=16){
        #pragma unroll
        for(int q=0;q<4;q++){
            int kk=kq*4+q;
            As[kk][lo]=w[(size_t)(c0+kk)*CH + obase+lo];
            Bs[kk][lo]=g_hB[base + (size_t)(c0+kk)*NP*NP];
        }
        __syncthreads();
        #pragma unroll
        for(int kk=0;kk<16;kk++){
            float4 a =*(const float4*)&As[kk][to*4];
            float4 bv=*(const float4*)&Bs[kk][tp*4];
            float av[4]={a.x,a.y,a.z,a.w};
            float bvv[4]={bv.x,bv.y,bv.z,bv.w};
            #pragma unroll
            for(int pi=0;pi<4;pi++)
                #pragma unroll
                for(int oj=0;oj<4;oj++)
                    acc[pi][oj]=fmaf(bvv[pi],av[oj],acc[pi][oj]);
        }
        __syncthreads();
    }
    #pragma unroll
    for(int pi=0;pi<4;pi++){
        float* fp=g_feat+(size_t)(pbase+tp*4+pi)*CH + obase+to*4;
        float4 o4;
        o4.x=gelu_f(acc[pi][0]+b[obase+to*4+0]);
        o4.y=gelu_f(acc[pi][1]+b[obase+to*4+1]);
        o4.z=gelu_f(acc[pi][2]+b[obase+to*4+2]);
        o4.w=gelu_f(acc[pi][3]+b[obase+to*4+3]);
        *(float4*)fp=o4;
    }
}

// ---- 4 heads: gelu(feat@W1k+b1)@W2k + b2 -> out ----
__global__ void __launch_bounds__(256) k_heads(const float* __restrict__ w1,
                                               const float* __restrict__ b1,
                                               const float* __restrict__ w2,
                                               const float* __restrict__ b2,
                                               float* __restrict__ out){
    __shared__ float Fs[32][65];
    __shared__ float Ws[32][64];
    __shared__ float red[64][17];
    int t=threadIdx.x;
    int pbase=blockIdx.x*64;
    int tp=t&15, td=t>>4;
    for(int k=0;k<4;k++){
        float acc[4][4];
        #pragma unroll
        for(int i=0;i<4;i++){ acc[i][0]=0.f; acc[i][1]=0.f; acc[i][2]=0.f; acc[i][3]=0.f; }
        for(int c0=0;c0<CH;c0+=32){
            for(int i=t;i<2048;i+=256){
                int r=i>>6, cc=i&63;
                Ws[r][cc]=w1[(size_t)k*CH*64 + (size_t)(c0+r)*64 + cc];
            }
            for(int i=t;i<2048;i+=256){
                int c=i&31, pl=i>>5;
                Fs[c][pl]=g_feat[(size_t)(pbase+pl)*CH + c0 + c];
            }
            __syncthreads();
            #pragma unroll 8
            for(int kk=0;kk<32;kk++){
                float4 a=*(const float4*)&Ws[kk][td*4];
                float av[4]={a.x,a.y,a.z,a.w};
                float f0=Fs[kk][tp*4+0], f1=Fs[kk][tp*4+1];
                float f2=Fs[kk][tp*4+2], f3=Fs[kk][tp*4+3];
                #pragma unroll
                for(int dj=0;dj<4;dj++){
                    acc[0][dj]=fmaf(f0,av[dj],acc[0][dj]);
                    acc[1][dj]=fmaf(f1,av[dj],acc[1][dj]);
                    acc[2][dj]=fmaf(f2,av[dj],acc[2][dj]);
                    acc[3][dj]=fmaf(f3,av[dj],acc[3][dj]);
                }
            }
            __syncthreads();
        }
        #pragma unroll
        for(int pi=0;pi<4;pi++){
            float v=0.f;
            #pragma unroll
            for(int dj=0;dj<4;dj++){
                int d=td*4+dj;
                float h1=gelu_f(acc[pi][dj]+b1[k*64+d]);
                v=fmaf(h1, w2[k*64+d], v);
            }
            red[tp*4+pi][td]=v;
        }
        __syncthreads();
        if(t<64){
            float v=b2[k];
            #pragma unroll
            for(int j=0;j<16;j++) v+=red[t][j];
            out[(size_t)k*NPOS + pbase + t]=v;
        }
        __syncthreads();
    }
}

extern "C" void kernel_launch(void* const* d_in, const int* in_sizes, int n_in,
                              void* d_out, int out_size){
    (void)in_sizes; (void)n_in; (void)out_size;
    const float* x     =(const float*)d_in[0];
    const float* fc0_w =(const float*)d_in[1];
    const float* fc0_b =(const float*)d_in[2];
    const float* sw1   =(const float*)d_in[3];
    const float* sw2   =(const float*)d_in[4];
    const float* w_w   =(const float*)d_in[5];
    const float* w_b   =(const float*)d_in[6];
    const float* fc1_w =(const float*)d_in[7];
    const float* fc1_b =(const float*)d_in[8];
    const float* h1w   =(const float*)d_in[9];
    const float* h1b   =(const float*)d_in[10];
    const float* h2w   =(const float*)d_in[11];
    const float* h2b   =(const float*)d_in[12];
    float* out=(float*)d_out;

    const int LIN_SMEM = (2*128*ASTR + 2*64*BSTR)*2;            // 71680
    const int DFT_SMEM = (2*128*DASTR + 2*64*DBSTR)*2;          // 51200
    const int IDF_SMEM = (2*128*IASTR + 2*48*IBSTR)*2;          // 54784
    cudaFuncSetAttribute(k_lin_mma,   cudaFuncAttributeMaxDynamicSharedMemorySize, LIN_SMEM);
    cudaFuncSetAttribute(k_dfty_mma,  cudaFuncAttributeMaxDynamicSharedMemorySize, DFT_SMEM);
    cudaFuncSetAttribute(k_idfty_mma, cudaFuncAttributeMaxDynamicSharedMemorySize, IDF_SMEM);

    k_tables<<<40,256>>>();
    k_packtw<<<48,256>>>();
    k_fc0<<<dim3(NP,NB),256>>>(x,fc0_w,fc0_b);
    for(int l=0;l<5;l++){
        int pp=l&1;
        k_dfty_mma <<<512,256,DFT_SMEM>>>(pp);
        k_dftx <<<NB*CH,800>>>();
        k_mix  <<<dim3(KXN,5),1024>>>(sw1,sw2,l);
        k_idftx<<<NB*CH,512>>>();
        k_idfty_mma<<<dim3(512,2),256,IDF_SMEM>>>(pp);
        k_lin_mma<<<dim3(512,1,NB),256,LIN_SMEM>>>(pp,w_w,w_b,l,(l<4)?1:0);
    }
    k_fc1  <<<dim3(NPOS/64,2),256>>>(fc1_w,fc1_b);
    k_heads<<<NPOS/64,256>>>(h1w,h1b,h2w,h2b,out);
}

// round 14
// speedup vs baseline: 1.7612x; 1.1659x over previous
#include <cuda_runtime.h>
#include <cuda_bf16.h>
#include <math.h>
#include <stdint.h>

#define NB 2
#define CH 128
#define NP 256
#define SS 240
#define MM 20
#define KXN 40
#define NPIX (SS*SS)
#define NPOS (NB*NPIX)
#define ASTR 72    // k_lin A row stride (bf16)
#define BSTR 136   // k_lin B row stride (bf16)
#define DASTR 72   // dfty A stride
#define DBSTR 56   // dfty B stride
#define IASTR 56   // idfty A stride
#define IBSTR 136  // idfty B stride
#define FASTR 136  // fc1 A ([c][o]) stride
#define FBSTR 136  // fc1/heads B stride
#define HASTR 72   // heads A ([c][d]) stride

// ---- scratch (device globals; no allocation allowed) ----
__device__ float  g_hA[NB*CH*NP*NP];
__device__ float  g_hB[NB*CH*NP*NP];
__device__ float2 g_Gy [NB*CH*NP*MM];
__device__ float2 g_Fm [NB*CH*KXN*MM];
__device__ float2 g_Fo [NB*CH*KXN*MM];
__device__ float2 g_Gy2[NB*CH*NP*MM];
__device__ float  g_feat[CH*NPOS];   // [o][p] layout
__device__ float2 g_csx [NP*KXN];
__device__ __nv_bfloat16 g_Tf_hi[NP*48], g_Tf_lo[NP*48];   // dfty  B: [y][n]
__device__ __nv_bfloat16 g_Ti_hi[48*NP], g_Ti_lo[48*NP];   // idfty B: [k][y]

__device__ __forceinline__ float gelu_f(float v){
    return 0.5f*v*(1.0f+erff(v*0.70710678118654752f));
}

// ================= warp-mma helpers =================
__device__ __forceinline__ uint32_t smem_u32(const void* p){
    uint32_t a;
    asm("{ .reg .u64 t; cvta.to.shared.u64 t, %1; cvt.u32.u64 %0, t; }" : "=r"(a) : "l"(p));
    return a;
}
__device__ __forceinline__ void ldmx4(uint32_t* r, uint32_t addr){
    asm volatile("ldmatrix.sync.aligned.m8n8.x4.shared.b16 {%0,%1,%2,%3}, [%4];"
        : "=r"(r[0]),"=r"(r[1]),"=r"(r[2]),"=r"(r[3]) : "r"(addr));
}
__device__ __forceinline__ void ldmx4t(uint32_t* r, uint32_t addr){
    asm volatile("ldmatrix.sync.aligned.m8n8.x4.trans.shared.b16 {%0,%1,%2,%3}, [%4];"
        : "=r"(r[0]),"=r"(r[1]),"=r"(r[2]),"=r"(r[3]) : "r"(addr));
}
__device__ __forceinline__ void ldmx2t(uint32_t* r, uint32_t addr){
    asm volatile("ldmatrix.sync.aligned.m8n8.x2.trans.shared.b16 {%0,%1}, [%2];"
        : "=r"(r[0]),"=r"(r[1]) : "r"(addr));
}
__device__ __forceinline__ void mma_bf16(float* c, const uint32_t* a, const uint32_t* b){
    asm volatile("mma.sync.aligned.m16n8k16.row.col.f32.bf16.bf16.f32 "
        "{%0,%1,%2,%3}, {%4,%5,%6,%7}, {%8,%9}, {%0,%1,%2,%3};"
        : "+f"(c[0]),"+f"(c[1]),"+f"(c[2]),"+f"(c[3])
        : "r"(a[0]),"r"(a[1]),"r"(a[2]),"r"(a[3]), "r"(b[0]),"r"(b[1]));
}
__device__ __forceinline__ uint32_t pkbf2(float lo, float hi){
    uint32_t r; asm("cvt.rn.bf16x2.f32 %0, %1, %2;" : "=r"(r) : "f"(hi), "f"(lo)); return r;
}
// split float4 into hi/lo bf16x2 pairs
__device__ __forceinline__ void split4(float4 v, uint2& hi, uint2& lo){
    uint32_t h0=pkbf2(v.x,v.y), h1=pkbf2(v.z,v.w);
    float r0=v.x-__uint_as_float(h0<<16);
    float r1=v.y-__uint_as_float(h0&0xFFFF0000u);
    float r2=v.z-__uint_as_float(h1<<16);
    float r3=v.w-__uint_as_float(h1&0xFFFF0000u);
    hi=make_uint2(h0,h1); lo=make_uint2(pkbf2(r0,r1),pkbf2(r2,r3));
}

// ---- twiddle tables ----
__global__ void k_tables(){
    int i = blockIdx.x*blockDim.x + threadIdx.x;
    if (i < NP*KXN){
        int xx=i/KXN, kxi=i%KXN;
        int kx = (kxi<MM)? kxi : 236+(kxi-MM);
        float s,c; sincospif((float)(kx*xx)*(1.0f/128.0f), &s, &c);
        g_csx[i]=make_float2(c,s);
    }
}
__global__ void k_packtw(){
    int n=blockIdx.x, y=threadIdx.x;
    float v=0.f;
    if(n<40){
        int ky=n>>1;
        float s,c; sincospif((float)(ky*y)*(1.0f/128.0f), &s, &c);
        v = (n&1)? -s : c;
    }
    __nv_bfloat16 hi=__float2bfloat16(v);
    __nv_bfloat16 lo=__float2bfloat16(v-__bfloat162float(hi));
    g_Tf_hi[y*48+n]=hi; g_Tf_lo[y*48+n]=lo;
    g_Ti_hi[n*NP+y]=hi; g_Ti_lo[n*NP+y]=lo;
}

// ---- fc0 + grid channels, write padded (b,c,x,y) into g_hA ----
__global__ void k_fc0(const float* __restrict__ x, const float* __restrict__ w,
                      const float* __restrict__ b){
    __shared__ float ws[5][CH];
    __shared__ float bs[CH];
    int t=threadIdx.x;
    for(int i=t;i<5*CH;i+=256) ws[i/CH][i%CH]=w[i];
    for(int i=t;i<CH;i+=256) bs[i]=b[i];
    __syncthreads();
    int xr=blockIdx.x, bb=blockIdx.y, y=t;
    bool inside=(xr<SS)&&(y<SS);
    float v0=0.f,v1=0.f,v2=0.f,v3=0.f,v4=0.f;
    if(inside){
        const float* xp=x+(((size_t)bb*SS+xr)*SS+y)*3;
        v0=xp[0]; v1=xp[1]; v2=xp[2];
        v3=(float)xr*(1.0f/239.0f);
        v4=(float)y *(1.0f/239.0f);
    }
    float* op=g_hA+(((size_t)bb*CH)*NP+xr)*NP+y;
    for(int c=0;c<CH;c++){
        float a=0.f;
        if(inside){
            a=bs[c];
            a=fmaf(v0,ws[0][c],a); a=fmaf(v1,ws[1][c],a); a=fmaf(v2,ws[2][c],a);
            a=fmaf(v3,ws[3][c],a); a=fmaf(v4,ws[4][c],a);
        }
        op[(size_t)c*NP*NP]=a;
    }
}

// ---- forward y-DFT via mma ----
__global__ void __launch_bounds__(256,2) k_dfty_mma(int pp){
    extern __shared__ __nv_bfloat16 smD[];
    __nv_bfloat16* Ahi=smD;
    __nv_bfloat16* Alo=Ahi+128*DASTR;
    __nv_bfloat16* Bhi=Alo+128*DASTR;
    __nv_bfloat16* Blo=Bhi+64*DBSTR;
    const float* h = pp? g_hB : g_hA;
    int t=threadIdx.x, lane=t&31, wid=t>>5;
    size_t rowbase=(size_t)blockIdx.x*128;
    const float* srow = h + rowbase*NP;
    float acc[6][4];
    #pragma unroll
    for(int ni=0;ni<6;ni++){ acc[ni][0]=0.f; acc[ni][1]=0.f; acc[ni][2]=0.f; acc[ni][3]=0.f; }
    uint32_t AhiB=smem_u32(Ahi), AloB=smem_u32(Alo);
    uint32_t BhiB=smem_u32(Bhi), BloB=smem_u32(Blo);
    int arow=lane&15;
    uint32_t acolb=(uint32_t)((lane>>4)<<4);
    int wm=wid*16;

    for(int kc=0;kc<4;kc++){
        #pragma unroll
        for(int i=0;i<8;i++){
            int idx=i*256+t; int r=idx>>4, c4=(idx&15)*4;
            uint2 hi,lo; split4(*(const float4*)(srow+(size_t)r*NP+kc*64+c4),hi,lo);
            *(uint2*)&Ahi[r*DASTR+c4]=hi;
            *(uint2*)&Alo[r*DASTR+c4]=lo;
        }
        #pragma unroll
        for(int i=0;i<6;i++){
            int idx=i*256+t; int k=idx/24, n2=(idx%24)*2;
            *(uint32_t*)&Bhi[k*DBSTR+n2]=*(const uint32_t*)&g_Tf_hi[(kc*64+k)*48+n2];
            *(uint32_t*)&Blo[k*DBSTR+n2]=*(const uint32_t*)&g_Tf_lo[(kc*64+k)*48+n2];
        }
        __syncthreads();
        #pragma unroll
        for(int kk=0;kk<4;kk++){
            uint32_t a[4];
            uint32_t aoff=(uint32_t)((wm+arow)*(2*DASTR)+kk*32)+acolb;
            ldmx4(a, AhiB+aoff);
            uint32_t bh[6][2], bl[6][2];
            #pragma unroll
            for(int ni=0;ni<6;ni++){
                uint32_t off=(uint32_t)((kk*16+arow)*(2*DBSTR)+ni*16);
                ldmx2t(bh[ni], BhiB+off);
                ldmx2t(bl[ni], BloB+off);
            }
            #pragma unroll
            for(int ni=0;ni<6;ni++){
                mma_bf16(acc[ni], a, bh[ni]);
                mma_bf16(acc[ni], a, bl[ni]);
            }
            uint32_t a2[4];
            ldmx4(a2, AloB+aoff);
            #pragma unroll
            for(int ni=0;ni<6;ni++)
                mma_bf16(acc[ni], a2, bh[ni]);
        }
        __syncthreads();
    }
    int r0=lane>>2, cq=lane&3;
    #pragma unroll
    for(int ni=0;ni<5;ni++){
        int ky=ni*4+cq;
        g_Gy[(rowbase+wm+r0  )*MM+ky]=make_float2(acc[ni][0],acc[ni][1]);
        g_Gy[(rowbase+wm+r0+8)*MM+ky]=make_float2(acc[ni][2],acc[ni][3]);
    }
}

// ---- forward x-DFT ----
__global__ void __launch_bounds__(800) k_dftx(){
    __shared__ float2 gsh[NP*MM];
    int bc=blockIdx.x, t=threadIdx.x;
    const float2* gp=g_Gy+(size_t)bc*NP*MM;
    for(int i=t;i<NP*MM;i+=800) gsh[i]=gp[i];
    __syncthreads();
    int kxi=t%KXN, ky=t/KXN;
    float ar=0.f, ai=0.f;
    #pragma unroll 4
    for(int xx=0;xx<NP;xx++){
        float2 w=g_csx[xx*KXN+kxi];
        float2 f=gsh[xx*MM+ky];
        ar += f.x*w.x + f.y*w.y;
        ai += f.y*w.x - f.x*w.y;
    }
    g_Fm[((size_t)bc*KXN+kxi)*MM+ky]=make_float2(ar,ai);
}

// ---- mode mixing ----
__global__ void __launch_bounds__(1024) k_mix(const float* __restrict__ w1,
                                              const float* __restrict__ w2, int l){
    __shared__ float2 fsh[2][CH][4];
    int kxi=blockIdx.x, myg=blockIdx.y, t=threadIdx.x;
    {
        int b=t>>9, rem=t&511, i=rem>>2, myl=rem&3;
        fsh[b][i][myl]=g_Fm[(((size_t)(b*CH+i))*KXN+kxi)*MM + myg*4+myl];
    }
    __syncthreads();
    int myl=t&3, b=(t>>2)&1, o=t>>3;
    int my=myg*4+myl;
    int mx=(kxi<MM)? kxi : (kxi-MM);
    const float2* wp=(const float2*)((kxi<MM)? w1 : w2);
    size_t base=(((size_t)l*CH*CH + o)*MM + mx)*MM + my;
    float ar=0.f, ai=0.f;
    #pragma unroll 4
    for(int i=0;i<CH;i++){
        float2 wv=wp[base+(size_t)i*CH*MM*MM];
        float2 f=fsh[b][i][myl];
        ar += f.x*wv.x - f.y*wv.y;
        ai += f.x*wv.y + f.y*wv.x;
    }
    g_Fo[(((size_t)(b*CH+o))*KXN+kxi)*MM+my]=make_float2(ar,ai);
}

// ---- inverse x-DFT ----
__global__ void __launch_bounds__(512) k_idftx(){
    __shared__ float2 fsh[KXN*MM];
    int bo=blockIdx.x, t=threadIdx.x;
    const float2* fp=g_Fo+(size_t)bo*KXN*MM;
    for(int i=t;i<KXN*MM;i+=512) fsh[i]=fp[i];
    __syncthreads();
    int xx=t&255, kg=t>>8;
    float ar[10], ai[10];
    #pragma unroll
    for(int j=0;j<10;j++){ ar[j]=0.f; ai[j]=0.f; }
    for(int k=0;k<KXN;k++){
        float2 w=g_csx[xx*KXN+k];
        #pragma unroll
        for(int j=0;j<10;j++){
            float2 f=fsh[k*MM+kg*10+j];
            ar[j] += f.x*w.x - f.y*w.y;
            ai[j] += f.x*w.y + f.y*w.x;
        }
    }
    float2* op=g_Gy2+((size_t)bo*NP+xx)*MM;
    #pragma unroll
    for(int j=0;j<10;j++){
        int ky=kg*10+j;
        float fk=((ky==0)?1.0f:2.0f)*(1.0f/65536.0f);
        op[ky]=make_float2(ar[j]*fk, ai[j]*fk);
    }
}

// ---- inverse y-DFT via mma ----
__global__ void __launch_bounds__(256,2) k_idfty_mma(int pp){
    extern __shared__ __nv_bfloat16 smI[];
    __nv_bfloat16* Ahi=smI;
    __nv_bfloat16* Alo=Ahi+128*IASTR;
    __nv_bfloat16* Bhi=Alo+128*IASTR;
    __nv_bfloat16* Blo=Bhi+48*IBSTR;
    float* dst = pp? g_hA : g_hB;
    int t=threadIdx.x, lane=t&31, wid=t>>5;
    size_t rowbase=(size_t)blockIdx.x*128;
    int nbase=blockIdx.y*128;
    const float* arow_g=(const float*)g_Gy2 + rowbase*2*MM;

    #pragma unroll
    for(int i=0;i<5;i++){
        int idx=i*256+t; int r=idx/10, j4=(idx%10)*4;
        uint2 hi,lo; split4(*(const float4*)(arow_g+(size_t)r*40+j4),hi,lo);
        *(uint2*)&Ahi[r*IASTR+j4]=hi;
        *(uint2*)&Alo[r*IASTR+j4]=lo;
    }
    #pragma unroll
    for(int i=0;i<4;i++){
        int idx=i*256+t; int r=idx>>3, c=idx&7;
        Ahi[r*IASTR+40+c]=__float2bfloat16(0.f);
        Alo[r*IASTR+40+c]=__float2bfloat16(0.f);
    }
    #pragma unroll
    for(int i=0;i<6;i++){
        int idx=i*256+t; int k=idx>>5, n4=(idx&31)*4;
        *(uint2*)&Bhi[k*IBSTR+n4]=*(const uint2*)&g_Ti_hi[k*NP+nbase+n4];
        *(uint2*)&Blo[k*IBSTR+n4]=*(const uint2*)&g_Ti_lo[k*NP+nbase+n4];
    }
    __syncthreads();

    int wm=(wid>>2)*64, wn=(wid&3)*32;
    float acc[4][4][4];
    #pragma unroll
    for(int mi=0;mi<4;mi++)
        #pragma unroll
        for(int ni=0;ni<4;ni++){
            acc[mi][ni][0]=0.f; acc[mi][ni][1]=0.f;
            acc[mi][ni][2]=0.f; acc[mi][ni][3]=0.f;
        }
    uint32_t AhiB=smem_u32(Ahi), AloB=smem_u32(Alo);
    uint32_t BhiB=smem_u32(Bhi), BloB=smem_u32(Blo);
    int arow=lane&15;
    uint32_t acolb=(uint32_t)((lane>>4)<<4);

    #pragma unroll
    for(int kk=0;kk<3;kk++){
        uint32_t a[4][4];
        #pragma unroll
        for(int mi=0;mi<4;mi++){
            uint32_t off=(uint32_t)((wm+mi*16+arow)*(2*IASTR)+kk*32)+acolb;
            ldmx4(a[mi], AhiB+off);
        }
        uint32_t bh[4][2], bl[4][2];
        #pragma unroll
        for(int ni=0;ni<4;ni++){
            uint32_t off=(uint32_t)((kk*16+arow)*(2*IBSTR)+(wn+ni*8)*2);
            ldmx2t(bh[ni], BhiB+off);
            ldmx2t(bl[ni], BloB+off);
        }
        #pragma unroll
        for(int mi=0;mi<4;mi++)
            #pragma unroll
            for(int ni=0;ni<4;ni++){
                mma_bf16(acc[mi][ni], a[mi], bh[ni]);
                mma_bf16(acc[mi][ni], a[mi], bl[ni]);
            }
        #pragma unroll
        for(int mi=0;mi<4;mi++){
            uint32_t off=(uint32_t)((wm+mi*16+arow)*(2*IASTR)+kk*32)+acolb;
            ldmx4(a[mi], AloB+off);
        }
        #pragma unroll
        for(int mi=0;mi<4;mi++)
            #pragma unroll
            for(int ni=0;ni<4;ni++)
                mma_bf16(acc[mi][ni], a[mi], bh[ni]);
    }

    int r0=lane>>2, c0=(lane&3)*2;
    #pragma unroll
    for(int mi=0;mi<4;mi++){
        size_t row0=rowbase+wm+mi*16+r0;
        #pragma unroll
        for(int ni=0;ni<4;ni++){
            int col=nbase+wn+ni*8+c0;
            *(float2*)&dst[row0*NP+col]    =make_float2(acc[mi][ni][0],acc[mi][ni][1]);
            *(float2*)&dst[(row0+8)*NP+col]=make_float2(acc[mi][ni][2],acc[mi][ni][3]);
        }
    }
}

// ---- 1x1 conv via mma.sync bf16 split (3-pass) ----
__global__ void __launch_bounds__(256,2) k_lin_mma(int pp, const float* __restrict__ ww,
                                                   const float* __restrict__ wb, int l, int dogelu){
    extern __shared__ __nv_bfloat16 sm[];
    __nv_bfloat16* Ahi = sm;
    __nv_bfloat16* Alo = Ahi + 128*ASTR;
    __nv_bfloat16* Bhi = Alo + 128*ASTR;
    __nv_bfloat16* Blo = Bhi + 64*BSTR;
    const float* src = pp ? g_hB : g_hA;
    float*       dst = pp ? g_hA : g_hB;
    int t=threadIdx.x, lane=t&31, wid=t>>5;
    int x=blockIdx.x>>1, ybase=(blockIdx.x&1)<<7, bb=blockIdx.z;
    const float* W = ww + (size_t)l*CH*CH;
    const float* srow = src + (((size_t)bb*CH)*NP + x)*NP + ybase;

    int wm=(wid>>2)*64, wn=(wid&3)*32;
    float acc[4][4][4];
    #pragma unroll
    for(int mi=0;mi<4;mi++)
        #pragma unroll
        for(int ni=0;ni<4;ni++){
            acc[mi][ni][0]=0.f; acc[mi][ni][1]=0.f;
            acc[mi][ni][2]=0.f; acc[mi][ni][3]=0.f;
        }
    uint32_t AhiB=smem_u32(Ahi), AloB=smem_u32(Alo);
    uint32_t BhiB=smem_u32(Bhi), BloB=smem_u32(Blo);
    int arow=lane&15;
    uint32_t acolb=(uint32_t)((lane>>4)<<4);

    for(int kc=0;kc<2;kc++){
        #pragma unroll
        for(int i=0;i<8;i++){
            int idx=i*256+t;
            int o=idx>>4, c4=(idx&15)*4;
            uint2 hi,lo; split4(*(const float4*)(W+(size_t)o*CH+kc*64+c4),hi,lo);
            *(uint2*)&Ahi[o*ASTR+c4]=hi;
            *(uint2*)&Alo[o*ASTR+c4]=lo;
        }
        #pragma unroll
        for(int i=0;i<8;i++){
            int idx=i*256+t;
            int c=idx>>5, y4=(idx&31)*4;
            uint2 hi,lo; split4(*(const float4*)(srow+(size_t)(kc*64+c)*NP*NP+y4),hi,lo);
            *(uint2*)&Bhi[c*BSTR+y4]=hi;
            *(uint2*)&Blo[c*BSTR+y4]=lo;
        }
        __syncthreads();
        #pragma unroll
        for(int kk=0;kk<4;kk++){
            uint32_t a[4][4];
            #pragma unroll
            for(int mi=0;mi<4;mi++){
                uint32_t off=(uint32_t)((wm+mi*16+arow)*(2*ASTR)+kk*32)+acolb;
                ldmx4(a[mi], AhiB+off);
            }
            uint32_t bh[4][2], bl[4][2];
            #pragma unroll
            for(int ni=0;ni<4;ni++){
                uint32_t off=(uint32_t)((kk*16+arow)*(2*BSTR)+(wn+ni*8)*2);
                ldmx2t(bh[ni], BhiB+off);
                ldmx2t(bl[ni], BloB+off);
            }
            #pragma unroll
            for(int mi=0;mi<4;mi++)
                #pragma unroll
                for(int ni=0;ni<4;ni++){
                    mma_bf16(acc[mi][ni], a[mi], bh[ni]);
                    mma_bf16(acc[mi][ni], a[mi], bl[ni]);
                }
            #pragma unroll
            for(int mi=0;mi<4;mi++){
                uint32_t off=(uint32_t)((wm+mi*16+arow)*(2*ASTR)+kk*32)+acolb;
                ldmx4(a[mi], AloB+off);
            }
            #pragma unroll
            for(int mi=0;mi<4;mi++)
                #pragma unroll
                for(int ni=0;ni<4;ni++)
                    mma_bf16(acc[mi][ni], a[mi], bh[ni]);
        }
        __syncthreads();
    }

    int r0=lane>>2, c0=(lane&3)*2;
    #pragma unroll
    for(int mi=0;mi<4;mi++){
        int o0=wm+mi*16+r0, o1=o0+8;
        float bias0=__ldg(wb+l*CH+o0), bias1=__ldg(wb+l*CH+o1);
        float* base0=dst+(((size_t)(bb*CH+o0))*NP+x)*NP+ybase;
        float* base1=dst+(((size_t)(bb*CH+o1))*NP+x)*NP+ybase;
        #pragma unroll
        for(int ni=0;ni<4;ni++){
            int y=wn+ni*8+c0;
            float2* p0=(float2*)(base0+y);
            float2 v0=*p0;
            v0.x+=acc[mi][ni][0]+bias0; v0.y+=acc[mi][ni][1]+bias0;
            if(dogelu){ v0.x=gelu_f(v0.x); v0.y=gelu_f(v0.y); }
            *p0=v0;
            float2* p1=(float2*)(base1+y);
            float2 v1=*p1;
            v1.x+=acc[mi][ni][2]+bias1; v1.y+=acc[mi][ni][3]+bias1;
            if(dogelu){ v1.x=gelu_f(v1.x); v1.y=gelu_f(v1.y); }
            *p1=v1;
        }
    }
}

// ---- fc1 via mma: feat[o][p] = gelu(W^T h + b), A loaded with ldmatrix.trans ----
// grid 960: bb(2) x xr(240) x yh(2); M=128 o, N=128 (120 live), K=128 in 2x64
__global__ void __launch_bounds__(256,2) k_fc1_mma(const float* __restrict__ w,
                                                   const float* __restrict__ b){
    extern __shared__ __nv_bfloat16 smF[];
    __nv_bfloat16* Ahi = smF;                 // [64 c][FASTR] (cols o)
    __nv_bfloat16* Alo = Ahi + 64*FASTR;
    __nv_bfloat16* Bhi = Alo + 64*FASTR;      // [64 c][FBSTR] (cols p)
    __nv_bfloat16* Blo = Bhi + 64*FBSTR;
    int t=threadIdx.x, lane=t&31, wid=t>>5;
    int bx=blockIdx.x;
    int bb=bx/480, rem=bx%480, xr=rem>>1, yh=rem&1;
    int pbase = bb*NPIX + xr*SS + yh*120;
    const float* srow = g_hB + (((size_t)bb*CH)*NP + xr)*NP + yh*120;

    int wm=(wid>>2)*64, wn=(wid&3)*32;
    float acc[4][4][4];
    #pragma unroll
    for(int mi=0;mi<4;mi++)
        #pragma unroll
        for(int ni=0;ni<4;ni++){
            acc[mi][ni][0]=0.f; acc[mi][ni][1]=0.f;
            acc[mi][ni][2]=0.f; acc[mi][ni][3]=0.f;
        }
    uint32_t AhiB=smem_u32(Ahi), AloB=smem_u32(Alo);
    uint32_t BhiB=smem_u32(Bhi), BloB=smem_u32(Blo);
    int arow=lane&15;
    int ktr=(lane&7)+((lane>>4)<<3);          // trans A: k-row within 16
    uint32_t mcolb=(uint32_t)(((lane>>3)&1)<<4);

    for(int kc=0;kc<2;kc++){
        #pragma unroll
        for(int i=0;i<8;i++){                 // A: [c][o], direct from w (K-major)
            int idx=i*256+t; int c=idx>>5, o4=(idx&31)*4;
            uint2 hi,lo; split4(*(const float4*)(w+(size_t)(kc*64+c)*CH+o4),hi,lo);
            *(uint2*)&Ahi[c*FASTR+o4]=hi;
            *(uint2*)&Alo[c*FASTR+o4]=lo;
        }
        #pragma unroll
        for(int i=0;i<8;i++){                 // B: h[c][y], pad y 120..127 with 0
            int idx=i*256+t; int c=idx>>5, y4=(idx&31)*4;
            uint2 hi=make_uint2(0,0), lo=make_uint2(0,0);
            if(y4<120) split4(*(const float4*)(srow+(size_t)(kc*64+c)*NP*NP+y4),hi,lo);
            *(uint2*)&Bhi[c*FBSTR+y4]=hi;
            *(uint2*)&Blo[c*FBSTR+y4]=lo;
        }
        __syncthreads();
        #pragma unroll
        for(int kk=0;kk<4;kk++){
            uint32_t a[4][4];
            #pragma unroll
            for(int mi=0;mi<4;mi++){
                uint32_t off=(uint32_t)((kk*16+ktr)*(2*FASTR)+(wm+mi*16)*2)+mcolb;
                ldmx4t(a[mi], AhiB+off);
            }
            uint32_t bh[4][2], bl[4][2];
            #pragma unroll
            for(int ni=0;ni<4;ni++){
                uint32_t off=(uint32_t)((kk*16+arow)*(2*FBSTR)+(wn+ni*8)*2);
                ldmx2t(bh[ni], BhiB+off);
                ldmx2t(bl[ni], BloB+off);
            }
            #pragma unroll
            for(int mi=0;mi<4;mi++)
                #pragma unroll
                for(int ni=0;ni<4;ni++){
                    mma_bf16(acc[mi][ni], a[mi], bh[ni]);
                    mma_bf16(acc[mi][ni], a[mi], bl[ni]);
                }
            #pragma unroll
            for(int mi=0;mi<4;mi++){
                uint32_t off=(uint32_t)((kk*16+ktr)*(2*FASTR)+(wm+mi*16)*2)+mcolb;
                ldmx4t(a[mi], AloB+off);
            }
            #pragma unroll
            for(int mi=0;mi<4;mi++)
                #pragma unroll
                for(int ni=0;ni<4;ni++)
                    mma_bf16(acc[mi][ni], a[mi], bh[ni]);
        }
        __syncthreads();
    }

    int r0=lane>>2, c0=(lane&3)*2;
    #pragma unroll
    for(int mi=0;mi<4;mi++){
        int o0=wm+mi*16+r0, o1=o0+8;
        float b0=__ldg(b+o0), b1v=__ldg(b+o1);
        #pragma unroll
        for(int ni=0;ni<4;ni++){
            int col=wn+ni*8+c0;
            if(col<120){
                *(float2*)&g_feat[(size_t)o0*NPOS+pbase+col]=
                    make_float2(gelu_f(acc[mi][ni][0]+b0), gelu_f(acc[mi][ni][1]+b0));
                *(float2*)&g_feat[(size_t)o1*NPOS+pbase+col]=
                    make_float2(gelu_f(acc[mi][ni][2]+b1v), gelu_f(acc[mi][ni][3]+b1v));
            }
        }
    }
}

// ---- 4 heads via mma: B=feat[c][p] staged once (K=128 resident), A=w1[c][d] trans ----
// grid 900 (NPOS/128); per head: M=64 d, N=128 p; epilogue folds gelu+dot(w2)+reduce
__global__ void __launch_bounds__(256,2) k_heads_mma(const float* __restrict__ w1,
                                                     const float* __restrict__ b1,
                                                     const float* __restrict__ w2,
                                                     const float* __restrict__ b2,
                                                     float* __restrict__ out){
    extern __shared__ __nv_bfloat16 smH[];
    __nv_bfloat16* Bhi = smH;                 // [128 c][FBSTR]
    __nv_bfloat16* Blo = Bhi + 128*FBSTR;
    __nv_bfloat16* Ahi = Blo + 128*FBSTR;     // [128 c][HASTR] (cols d)
    __nv_bfloat16* Alo = Ahi + 128*HASTR;
    int t=threadIdx.x, lane=t&31, wid=t>>5;
    int pbase=blockIdx.x*128;
    uint32_t AhiB=smem_u32(Ahi), AloB=smem_u32(Alo);
    uint32_t BhiB=smem_u32(Bhi), BloB=smem_u32(Blo);
    int arow=lane&15;
    int ktr=(lane&7)+((lane>>4)<<3);
    uint32_t mcolb=(uint32_t)(((lane>>3)&1)<<4);
    int wn=wid*16;

    #pragma unroll
    for(int i=0;i<16;i++){                    // B: feat[c][p], K=128 full
        int idx=i*256+t; int c=idx>>5, p4=(idx&31)*4;
        uint2 hi,lo; split4(*(const float4*)(g_feat+(size_t)c*NPOS+pbase+p4),hi,lo);
        *(uint2*)&Bhi[c*FBSTR+p4]=hi;
        *(uint2*)&Blo[c*FBSTR+p4]=lo;
    }

    for(int k=0;k<4;k++){
        #pragma unroll
        for(int i=0;i<8;i++){                 // A: w1[k][c][d]
            int idx=i*256+t; int c=idx>>4, d4=(idx&15)*4;
            uint2 hi,lo; split4(*(const float4*)(w1+(size_t)k*CH*64+(size_t)c*64+d4),hi,lo);
            *(uint2*)&Ahi[c*HASTR+d4]=hi;
            *(uint2*)&Alo[c*HASTR+d4]=lo;
        }
        __syncthreads();

        float acc[4][2][4];                   // mi=4 (d), ni=2 (p 16)
        #pragma unroll
        for(int mi=0;mi<4;mi++)
            #pragma unroll
            for(int ni=0;ni<2;ni++){
                acc[mi][ni][0]=0.f; acc[mi][ni][1]=0.f;
                acc[mi][ni][2]=0.f; acc[mi][ni][3]=0.f;
            }
        #pragma unroll
        for(int kk=0;kk<8;kk++){
            uint32_t a[4][4];
            #pragma unroll
            for(int mi=0;mi<4;mi++){
                uint32_t off=(uint32_t)((kk*16+ktr)*(2*HASTR)+(mi*16)*2)+mcolb;
                ldmx4t(a[mi], AhiB+off);
            }
            uint32_t bh[2][2], bl[2][2];
            #pragma unroll
            for(int ni=0;ni<2;ni++){
                uint32_t off=(uint32_t)((kk*16+arow)*(2*FBSTR)+(wn+ni*8)*2);
                ldmx2t(bh[ni], BhiB+off);
                ldmx2t(bl[ni], BloB+off);
            }
            #pragma unroll
            for(int mi=0;mi<4;mi++)
                #pragma unroll
                for(int ni=0;ni<2;ni++){
                    mma_bf16(acc[mi][ni], a[mi], bh[ni]);
                    mma_bf16(acc[mi][ni], a[mi], bl[ni]);
                }
            #pragma unroll
            for(int mi=0;mi<4;mi++){
                uint32_t off=(uint32_t)((kk*16+ktr)*(2*HASTR)+(mi*16)*2)+mcolb;
                ldmx4t(a[mi], AloB+off);
            }
            #pragma unroll
            for(int mi=0;mi<4;mi++)
                #pragma unroll
                for(int ni=0;ni<2;ni++)
                    mma_bf16(acc[mi][ni], a[mi], bh[ni]);
        }

        // epilogue: gelu(acc + b1) dot w2, reduce over d (rows), write out
        int r0=lane>>2;
        #pragma unroll
        for(int ni=0;ni<2;ni++){
            float s0=0.f, s1=0.f;
            #pragma unroll
            for(int mi=0;mi<4;mi++){
                int d0=mi*16+r0, d1=d0+8;
                float w0=__ldg(w2+k*64+d0), w1v=__ldg(w2+k*64+d1);
                float bb0=__ldg(b1+k*64+d0), bb1=__ldg(b1+k*64+d1);
                s0=fmaf(gelu_f(acc[mi][ni][0]+bb0),w0,s0);
                s0=fmaf(gelu_f(acc[mi][ni][2]+bb1),w1v,s0);
                s1=fmaf(gelu_f(acc[mi][ni][1]+bb0),w0,s1);
                s1=fmaf(gelu_f(acc[mi][ni][3]+bb1),w1v,s1);
            }
            #pragma unroll
            for(int m=4;m<=16;m<<=1){
                s0+=__shfl_xor_sync(0xFFFFFFFFu,s0,m);
                s1+=__shfl_xor_sync(0xFFFFFFFFu,s1,m);
            }
            if((lane>>2)==0){
                int p=pbase+wn+ni*8+(lane&3)*2;
                float bk=__ldg(b2+k);
                out[(size_t)k*NPOS+p  ]=s0+bk;
                out[(size_t)k*NPOS+p+1]=s1+bk;
            }
        }
        __syncthreads();
    }
}

extern "C" void kernel_launch(void* const* d_in, const int* in_sizes, int n_in,
                              void* d_out, int out_size){
    (void)in_sizes; (void)n_in; (void)out_size;
    const float* x     =(const float*)d_in[0];
    const float* fc0_w =(const float*)d_in[1];
    const float* fc0_b =(const float*)d_in[2];
    const float* sw1   =(const float*)d_in[3];
    const float* sw2   =(const float*)d_in[4];
    const float* w_w   =(const float*)d_in[5];
    const float* w_b   =(const float*)d_in[6];
    const float* fc1_w =(const float*)d_in[7];
    const float* fc1_b =(const float*)d_in[8];
    const float* h1w   =(const float*)d_in[9];
    const float* h1b   =(const float*)d_in[10];
    const float* h2w   =(const float*)d_in[11];
    const float* h2b   =(const float*)d_in[12];
    float* out=(float*)d_out;

    const int LIN_SMEM = (2*128*ASTR + 2*64*BSTR)*2;            // 71680
    const int DFT_SMEM = (2*128*DASTR + 2*64*DBSTR)*2;          // 51200
    const int IDF_SMEM = (2*128*IASTR + 2*48*IBSTR)*2;          // 54784
    const int FC1_SMEM = (2*64*FASTR + 2*64*FBSTR)*2;           // 69632
    const int HED_SMEM = (2*128*FBSTR + 2*128*HASTR)*2;         // 106496
    cudaFuncSetAttribute(k_lin_mma,   cudaFuncAttributeMaxDynamicSharedMemorySize, LIN_SMEM);
    cudaFuncSetAttribute(k_dfty_mma,  cudaFuncAttributeMaxDynamicSharedMemorySize, DFT_SMEM);
    cudaFuncSetAttribute(k_idfty_mma, cudaFuncAttributeMaxDynamicSharedMemorySize, IDF_SMEM);
    cudaFuncSetAttribute(k_fc1_mma,   cudaFuncAttributeMaxDynamicSharedMemorySize, FC1_SMEM);
    cudaFuncSetAttribute(k_heads_mma, cudaFuncAttributeMaxDynamicSharedMemorySize, HED_SMEM);

    k_tables<<<40,256>>>();
    k_packtw<<<48,256>>>();
    k_fc0<<<dim3(NP,NB),256>>>(x,fc0_w,fc0_b);
    for(int l=0;l<5;l++){
        int pp=l&1;
        k_dfty_mma <<<512,256,DFT_SMEM>>>(pp);
        k_dftx <<<NB*CH,800>>>();
        k_mix  <<<dim3(KXN,5),1024>>>(sw1,sw2,l);
        k_idftx<<<NB*CH,512>>>();
        k_idfty_mma<<<dim3(512,2),256,IDF_SMEM>>>(pp);
        k_lin_mma<<<dim3(512,1,NB),256,LIN_SMEM>>>(pp,w_w,w_b,l,(l<4)?1:0);
    }
    k_fc1_mma  <<<960,256,FC1_SMEM>>>(fc1_w,fc1_b);
    k_heads_mma<<<900,256,HED_SMEM>>>(h1w,h1b,h2w,h2b,out);
}

// round 15
// speedup vs baseline: 2.0383x; 1.1573x over previous
#include <cuda_runtime.h>
#include <cuda_bf16.h>
#include <math.h>
#include <stdint.h>

#define NB 2
#define CH 128
#define NP 256
#define SS 240
#define MM 20
#define KXN 40
#define NPIX (SS*SS)
#define NPOS (NB*NPIX)
#define ASTR 72    // k_lin A row stride (bf16)
#define BSTR 136   // k_lin B row stride (bf16)
#define DASTR 72   // dfty A stride
#define DBSTR 56   // dfty B stride
#define FASTR 136  // fc1 A ([c][o]) stride
#define FBSTR 136  // fc1/heads B stride
#define HASTR 72   // heads A ([c][d]) stride

// ---- scratch (device globals; no allocation allowed) ----
__device__ float  g_hA[NB*CH*NP*NP];
__device__ float  g_hB[NB*CH*NP*NP];
__device__ float2 g_Gy [NB*CH*NP*MM];
__device__ float2 g_Fm [NB*CH*KXN*MM];
__device__ float2 g_Fo [NB*CH*KXN*MM];
__device__ float2 g_Gy2[NB*CH*NP*MM];
__device__ float  g_feat[CH*NPOS];   // [o][p] layout
__device__ float2 g_csx [NP*KXN];
__device__ __nv_bfloat16 g_Tf_hi[NP*48], g_Tf_lo[NP*48];   // dfty  B: [y][n]
__device__ __nv_bfloat16 g_Ti_hi[48*NP], g_Ti_lo[48*NP];   // idfty B: [k][y]

__device__ __forceinline__ float gelu_f(float v){
    return 0.5f*v*(1.0f+erff(v*0.70710678118654752f));
}

// ================= warp-mma helpers =================
__device__ __forceinline__ uint32_t smem_u32(const void* p){
    uint32_t a;
    asm("{ .reg .u64 t; cvta.to.shared.u64 t, %1; cvt.u32.u64 %0, t; }" : "=r"(a) : "l"(p));
    return a;
}
__device__ __forceinline__ void ldmx4(uint32_t* r, uint32_t addr){
    asm volatile("ldmatrix.sync.aligned.m8n8.x4.shared.b16 {%0,%1,%2,%3}, [%4];"
        : "=r"(r[0]),"=r"(r[1]),"=r"(r[2]),"=r"(r[3]) : "r"(addr));
}
__device__ __forceinline__ void ldmx4t(uint32_t* r, uint32_t addr){
    asm volatile("ldmatrix.sync.aligned.m8n8.x4.trans.shared.b16 {%0,%1,%2,%3}, [%4];"
        : "=r"(r[0]),"=r"(r[1]),"=r"(r[2]),"=r"(r[3]) : "r"(addr));
}
__device__ __forceinline__ void ldmx2t(uint32_t* r, uint32_t addr){
    asm volatile("ldmatrix.sync.aligned.m8n8.x2.trans.shared.b16 {%0,%1}, [%2];"
        : "=r"(r[0]),"=r"(r[1]) : "r"(addr));
}
__device__ __forceinline__ void mma_bf16(float* c, const uint32_t* a, const uint32_t* b){
    asm volatile("mma.sync.aligned.m16n8k16.row.col.f32.bf16.bf16.f32 "
        "{%0,%1,%2,%3}, {%4,%5,%6,%7}, {%8,%9}, {%0,%1,%2,%3};"
        : "+f"(c[0]),"+f"(c[1]),"+f"(c[2]),"+f"(c[3])
        : "r"(a[0]),"r"(a[1]),"r"(a[2]),"r"(a[3]), "r"(b[0]),"r"(b[1]));
}
__device__ __forceinline__ uint32_t pkbf2(float lo, float hi){
    uint32_t r; asm("cvt.rn.bf16x2.f32 %0, %1, %2;" : "=r"(r) : "f"(hi), "f"(lo)); return r;
}
__device__ __forceinline__ void split4(float4 v, uint2& hi, uint2& lo){
    uint32_t h0=pkbf2(v.x,v.y), h1=pkbf2(v.z,v.w);
    float r0=v.x-__uint_as_float(h0<<16);
    float r1=v.y-__uint_as_float(h0&0xFFFF0000u);
    float r2=v.z-__uint_as_float(h1<<16);
    float r3=v.w-__uint_as_float(h1&0xFFFF0000u);
    hi=make_uint2(h0,h1); lo=make_uint2(pkbf2(r0,r1),pkbf2(r2,r3));
}

// ---- twiddle tables ----
__global__ void k_tables(){
    int i = blockIdx.x*blockDim.x + threadIdx.x;
    if (i < NP*KXN){
        int xx=i/KXN, kxi=i%KXN;
        int kx = (kxi<MM)? kxi : 236+(kxi-MM);
        float s,c; sincospif((float)(kx*xx)*(1.0f/128.0f), &s, &c);
        g_csx[i]=make_float2(c,s);
    }
}
__global__ void k_packtw(){
    int n=blockIdx.x, y=threadIdx.x;
    float v=0.f;
    if(n<40){
        int ky=n>>1;
        float s,c; sincospif((float)(ky*y)*(1.0f/128.0f), &s, &c);
        v = (n&1)? -s : c;
    }
    __nv_bfloat16 hi=__float2bfloat16(v);
    __nv_bfloat16 lo=__float2bfloat16(v-__bfloat162float(hi));
    g_Tf_hi[y*48+n]=hi; g_Tf_lo[y*48+n]=lo;
    g_Ti_hi[n*NP+y]=hi; g_Ti_lo[n*NP+y]=lo;
}

// ---- fc0 + grid channels, write padded (b,c,x,y) into g_hA ----
__global__ void k_fc0(const float* __restrict__ x, const float* __restrict__ w,
                      const float* __restrict__ b){
    __shared__ float ws[5][CH];
    __shared__ float bs[CH];
    int t=threadIdx.x;
    for(int i=t;i<5*CH;i+=256) ws[i/CH][i%CH]=w[i];
    for(int i=t;i<CH;i+=256) bs[i]=b[i];
    __syncthreads();
    int xr=blockIdx.x, bb=blockIdx.y, y=t;
    bool inside=(xr<SS)&&(y<SS);
    float v0=0.f,v1=0.f,v2=0.f,v3=0.f,v4=0.f;
    if(inside){
        const float* xp=x+(((size_t)bb*SS+xr)*SS+y)*3;
        v0=xp[0]; v1=xp[1]; v2=xp[2];
        v3=(float)xr*(1.0f/239.0f);
        v4=(float)y *(1.0f/239.0f);
    }
    float* op=g_hA+(((size_t)bb*CH)*NP+xr)*NP+y;
    for(int c=0;c<CH;c++){
        float a=0.f;
        if(inside){
            a=bs[c];
            a=fmaf(v0,ws[0][c],a); a=fmaf(v1,ws[1][c],a); a=fmaf(v2,ws[2][c],a);
            a=fmaf(v3,ws[3][c],a); a=fmaf(v4,ws[4][c],a);
        }
        op[(size_t)c*NP*NP]=a;
    }
}

// ---- forward y-DFT via mma ----
__global__ void __launch_bounds__(256,2) k_dfty_mma(int pp){
    extern __shared__ __nv_bfloat16 smD[];
    __nv_bfloat16* Ahi=smD;
    __nv_bfloat16* Alo=Ahi+128*DASTR;
    __nv_bfloat16* Bhi=Alo+128*DASTR;
    __nv_bfloat16* Blo=Bhi+64*DBSTR;
    const float* h = pp? g_hB : g_hA;
    int t=threadIdx.x, lane=t&31, wid=t>>5;
    size_t rowbase=(size_t)blockIdx.x*128;
    const float* srow = h + rowbase*NP;
    float acc[6][4];
    #pragma unroll
    for(int ni=0;ni<6;ni++){ acc[ni][0]=0.f; acc[ni][1]=0.f; acc[ni][2]=0.f; acc[ni][3]=0.f; }
    uint32_t AhiB=smem_u32(Ahi), AloB=smem_u32(Alo);
    uint32_t BhiB=smem_u32(Bhi), BloB=smem_u32(Blo);
    int arow=lane&15;
    uint32_t acolb=(uint32_t)((lane>>4)<<4);
    int wm=wid*16;

    for(int kc=0;kc<4;kc++){
        #pragma unroll
        for(int i=0;i<8;i++){
            int idx=i*256+t; int r=idx>>4, c4=(idx&15)*4;
            uint2 hi,lo; split4(*(const float4*)(srow+(size_t)r*NP+kc*64+c4),hi,lo);
            *(uint2*)&Ahi[r*DASTR+c4]=hi;
            *(uint2*)&Alo[r*DASTR+c4]=lo;
        }
        #pragma unroll
        for(int i=0;i<6;i++){
            int idx=i*256+t; int k=idx/24, n2=(idx%24)*2;
            *(uint32_t*)&Bhi[k*DBSTR+n2]=*(const uint32_t*)&g_Tf_hi[(kc*64+k)*48+n2];
            *(uint32_t*)&Blo[k*DBSTR+n2]=*(const uint32_t*)&g_Tf_lo[(kc*64+k)*48+n2];
        }
        __syncthreads();
        #pragma unroll
        for(int kk=0;kk<4;kk++){
            uint32_t a[4];
            uint32_t aoff=(uint32_t)((wm+arow)*(2*DASTR)+kk*32)+acolb;
            ldmx4(a, AhiB+aoff);
            uint32_t bh[6][2], bl[6][2];
            #pragma unroll
            for(int ni=0;ni<6;ni++){
                uint32_t off=(uint32_t)((kk*16+arow)*(2*DBSTR)+ni*16);
                ldmx2t(bh[ni], BhiB+off);
                ldmx2t(bl[ni], BloB+off);
            }
            #pragma unroll
            for(int ni=0;ni<6;ni++){
                mma_bf16(acc[ni], a, bh[ni]);
                mma_bf16(acc[ni], a, bl[ni]);
            }
            uint32_t a2[4];
            ldmx4(a2, AloB+aoff);
            #pragma unroll
            for(int ni=0;ni<6;ni++)
                mma_bf16(acc[ni], a2, bh[ni]);
        }
        __syncthreads();
    }
    int r0=lane>>2, cq=lane&3;
    #pragma unroll
    for(int ni=0;ni<5;ni++){
        int ky=ni*4+cq;
        g_Gy[(rowbase+wm+r0  )*MM+ky]=make_float2(acc[ni][0],acc[ni][1]);
        g_Gy[(rowbase+wm+r0+8)*MM+ky]=make_float2(acc[ni][2],acc[ni][3]);
    }
}

// ---- forward x-DFT ----
__global__ void __launch_bounds__(800) k_dftx(){
    __shared__ float2 gsh[NP*MM];
    int bc=blockIdx.x, t=threadIdx.x;
    const float2* gp=g_Gy+(size_t)bc*NP*MM;
    for(int i=t;i<NP*MM;i+=800) gsh[i]=gp[i];
    __syncthreads();
    int kxi=t%KXN, ky=t/KXN;
    float ar=0.f, ai=0.f;
    #pragma unroll 4
    for(int xx=0;xx<NP;xx++){
        float2 w=g_csx[xx*KXN+kxi];
        float2 f=gsh[xx*MM+ky];
        ar += f.x*w.x + f.y*w.y;
        ai += f.y*w.x - f.x*w.y;
    }
    g_Fm[((size_t)bc*KXN+kxi)*MM+ky]=make_float2(ar,ai);
}

// ---- mode mixing ----
__global__ void __launch_bounds__(1024) k_mix(const float* __restrict__ w1,
                                              const float* __restrict__ w2, int l){
    __shared__ float2 fsh[2][CH][4];
    int kxi=blockIdx.x, myg=blockIdx.y, t=threadIdx.x;
    {
        int b=t>>9, rem=t&511, i=rem>>2, myl=rem&3;
        fsh[b][i][myl]=g_Fm[(((size_t)(b*CH+i))*KXN+kxi)*MM + myg*4+myl];
    }
    __syncthreads();
    int myl=t&3, b=(t>>2)&1, o=t>>3;
    int my=myg*4+myl;
    int mx=(kxi<MM)? kxi : (kxi-MM);
    const float2* wp=(const float2*)((kxi<MM)? w1 : w2);
    size_t base=(((size_t)l*CH*CH + o)*MM + mx)*MM + my;
    float ar=0.f, ai=0.f;
    #pragma unroll 4
    for(int i=0;i<CH;i++){
        float2 wv=wp[base+(size_t)i*CH*MM*MM];
        float2 f=fsh[b][i][myl];
        ar += f.x*wv.x - f.y*wv.y;
        ai += f.x*wv.y + f.y*wv.x;
    }
    g_Fo[(((size_t)(b*CH+o))*KXN+kxi)*MM+my]=make_float2(ar,ai);
}

// ---- inverse x-DFT ----
__global__ void __launch_bounds__(512) k_idftx(){
    __shared__ float2 fsh[KXN*MM];
    int bo=blockIdx.x, t=threadIdx.x;
    const float2* fp=g_Fo+(size_t)bo*KXN*MM;
    for(int i=t;i<KXN*MM;i+=512) fsh[i]=fp[i];
    __syncthreads();
    int xx=t&255, kg=t>>8;
    float ar[10], ai[10];
    #pragma unroll
    for(int j=0;j<10;j++){ ar[j]=0.f; ai[j]=0.f; }
    for(int k=0;k<KXN;k++){
        float2 w=g_csx[xx*KXN+k];
        #pragma unroll
        for(int j=0;j<10;j++){
            float2 f=fsh[k*MM+kg*10+j];
            ar[j] += f.x*w.x - f.y*w.y;
            ai[j] += f.x*w.y + f.y*w.x;
        }
    }
    float2* op=g_Gy2+((size_t)bo*NP+xx)*MM;
    #pragma unroll
    for(int j=0;j<10;j++){
        int ky=kg*10+j;
        float fk=((ky==0)?1.0f:2.0f)*(1.0f/65536.0f);
        op[ky]=make_float2(ar[j]*fk, ai[j]*fk);
    }
}

// ---- 1x1 conv + FUSED inverse y-DFT via mma (3 chunks: lin-k0, lin-k1, spec-K48) ----
// grid (512,1,NB), 256 threads = 8 warps (2 M x 4 N); dst is WRITE-ONLY
__global__ void __launch_bounds__(256,2) k_lin_mma(int pp, const float* __restrict__ ww,
                                                   const float* __restrict__ wb, int l, int dogelu){
    extern __shared__ __nv_bfloat16 sm[];
    __nv_bfloat16* Ahi = sm;
    __nv_bfloat16* Alo = Ahi + 128*ASTR;
    __nv_bfloat16* Bhi = Alo + 128*ASTR;
    __nv_bfloat16* Blo = Bhi + 64*BSTR;
    const float* src = pp ? g_hB : g_hA;
    float*       dst = pp ? g_hA : g_hB;
    int t=threadIdx.x, lane=t&31, wid=t>>5;
    int x=blockIdx.x>>1, ybase=(blockIdx.x&1)<<7, bb=blockIdx.z;
    const float* W = ww + (size_t)l*CH*CH;
    const float* srow = src + (((size_t)bb*CH)*NP + x)*NP + ybase;

    int wm=(wid>>2)*64, wn=(wid&3)*32;
    float acc[4][4][4];
    #pragma unroll
    for(int mi=0;mi<4;mi++)
        #pragma unroll
        for(int ni=0;ni<4;ni++){
            acc[mi][ni][0]=0.f; acc[mi][ni][1]=0.f;
            acc[mi][ni][2]=0.f; acc[mi][ni][3]=0.f;
        }
    uint32_t AhiB=smem_u32(Ahi), AloB=smem_u32(Alo);
    uint32_t BhiB=smem_u32(Bhi), BloB=smem_u32(Blo);
    int arow=lane&15;
    uint32_t acolb=(uint32_t)((lane>>4)<<4);

    for(int kc=0;kc<3;kc++){
        if(kc<2){
            #pragma unroll
            for(int i=0;i<8;i++){
                int idx=i*256+t;
                int o=idx>>4, c4=(idx&15)*4;
                uint2 hi,lo; split4(*(const float4*)(W+(size_t)o*CH+kc*64+c4),hi,lo);
                *(uint2*)&Ahi[o*ASTR+c4]=hi;
                *(uint2*)&Alo[o*ASTR+c4]=lo;
            }
            #pragma unroll
            for(int i=0;i<8;i++){
                int idx=i*256+t;
                int c=idx>>5, y4=(idx&31)*4;
                uint2 hi,lo; split4(*(const float4*)(srow+(size_t)(kc*64+c)*NP*NP+y4),hi,lo);
                *(uint2*)&Bhi[c*BSTR+y4]=hi;
                *(uint2*)&Blo[c*BSTR+y4]=lo;
            }
        } else {
            // spec chunk: A = Gy2[(bb,o,x)][k], 40 live + 8 pad; B = Ti[k][ybase+y]
            #pragma unroll
            for(int i=0;i<5;i++){
                int idx=i*256+t; int r=idx/10, j4=(idx%10)*4;
                const float* gp=(const float*)g_Gy2 + (((size_t)(bb*CH+r))*NP + x)*2*MM;
                uint2 hi,lo; split4(*(const float4*)(gp+j4),hi,lo);
                *(uint2*)&Ahi[r*ASTR+j4]=hi;
                *(uint2*)&Alo[r*ASTR+j4]=lo;
            }
            #pragma unroll
            for(int i=0;i<4;i++){
                int idx=i*256+t; int r=idx>>3, c=idx&7;
                Ahi[r*ASTR+40+c]=__float2bfloat16(0.f);
                Alo[r*ASTR+40+c]=__float2bfloat16(0.f);
            }
            #pragma unroll
            for(int i=0;i<6;i++){
                int idx=i*256+t; int k=idx>>5, n4=(idx&31)*4;
                *(uint2*)&Bhi[k*BSTR+n4]=*(const uint2*)&g_Ti_hi[k*NP+ybase+n4];
                *(uint2*)&Blo[k*BSTR+n4]=*(const uint2*)&g_Ti_lo[k*NP+ybase+n4];
            }
        }
        __syncthreads();
        int kmax=(kc<2)?4:3;
        for(int kk=0;kk<kmax;kk++){
            uint32_t a[4][4];
            #pragma unroll
            for(int mi=0;mi<4;mi++){
                uint32_t off=(uint32_t)((wm+mi*16+arow)*(2*ASTR)+kk*32)+acolb;
                ldmx4(a[mi], AhiB+off);
            }
            uint32_t bh[4][2], bl[4][2];
            #pragma unroll
            for(int ni=0;ni<4;ni++){
                uint32_t off=(uint32_t)((kk*16+arow)*(2*BSTR)+(wn+ni*8)*2);
                ldmx2t(bh[ni], BhiB+off);
                ldmx2t(bl[ni], BloB+off);
            }
            #pragma unroll
            for(int mi=0;mi<4;mi++)
                #pragma unroll
                for(int ni=0;ni<4;ni++){
                    mma_bf16(acc[mi][ni], a[mi], bh[ni]);
                    mma_bf16(acc[mi][ni], a[mi], bl[ni]);
                }
            #pragma unroll
            for(int mi=0;mi<4;mi++){
                uint32_t off=(uint32_t)((wm+mi*16+arow)*(2*ASTR)+kk*32)+acolb;
                ldmx4(a[mi], AloB+off);
            }
            #pragma unroll
            for(int mi=0;mi<4;mi++)
                #pragma unroll
                for(int ni=0;ni<4;ni++)
                    mma_bf16(acc[mi][ni], a[mi], bh[ni]);
        }
        __syncthreads();
    }

    int r0=lane>>2, c0=(lane&3)*2;
    #pragma unroll
    for(int mi=0;mi<4;mi++){
        int o0=wm+mi*16+r0, o1=o0+8;
        float bias0=__ldg(wb+l*CH+o0), bias1=__ldg(wb+l*CH+o1);
        float* base0=dst+(((size_t)(bb*CH+o0))*NP+x)*NP+ybase;
        float* base1=dst+(((size_t)(bb*CH+o1))*NP+x)*NP+ybase;
        #pragma unroll
        for(int ni=0;ni<4;ni++){
            int y=wn+ni*8+c0;
            float2 v0=make_float2(acc[mi][ni][0]+bias0, acc[mi][ni][1]+bias0);
            float2 v1=make_float2(acc[mi][ni][2]+bias1, acc[mi][ni][3]+bias1);
            if(dogelu){
                v0.x=gelu_f(v0.x); v0.y=gelu_f(v0.y);
                v1.x=gelu_f(v1.x); v1.y=gelu_f(v1.y);
            }
            *(float2*)(base0+y)=v0;
            *(float2*)(base1+y)=v1;
        }
    }
}

// ---- fc1 via mma: feat[o][p] = gelu(W^T h + b) ----
__global__ void __launch_bounds__(256,2) k_fc1_mma(const float* __restrict__ w,
                                                   const float* __restrict__ b){
    extern __shared__ __nv_bfloat16 smF[];
    __nv_bfloat16* Ahi = smF;
    __nv_bfloat16* Alo = Ahi + 64*FASTR;
    __nv_bfloat16* Bhi = Alo + 64*FASTR;
    __nv_bfloat16* Blo = Bhi + 64*FBSTR;
    int t=threadIdx.x, lane=t&31, wid=t>>5;
    int bx=blockIdx.x;
    int bb=bx/480, rem=bx%480, xr=rem>>1, yh=rem&1;
    int pbase = bb*NPIX + xr*SS + yh*120;
    const float* srow = g_hB + (((size_t)bb*CH)*NP + xr)*NP + yh*120;

    int wm=(wid>>2)*64, wn=(wid&3)*32;
    float acc[4][4][4];
    #pragma unroll
    for(int mi=0;mi<4;mi++)
        #pragma unroll
        for(int ni=0;ni<4;ni++){
            acc[mi][ni][0]=0.f; acc[mi][ni][1]=0.f;
            acc[mi][ni][2]=0.f; acc[mi][ni][3]=0.f;
        }
    uint32_t AhiB=smem_u32(Ahi), AloB=smem_u32(Alo);
    uint32_t BhiB=smem_u32(Bhi), BloB=smem_u32(Blo);
    int arow=lane&15;
    int ktr=(lane&7)+((lane>>4)<<3);
    uint32_t mcolb=(uint32_t)(((lane>>3)&1)<<4);

    for(int kc=0;kc<2;kc++){
        #pragma unroll
        for(int i=0;i<8;i++){
            int idx=i*256+t; int c=idx>>5, o4=(idx&31)*4;
            uint2 hi,lo; split4(*(const float4*)(w+(size_t)(kc*64+c)*CH+o4),hi,lo);
            *(uint2*)&Ahi[c*FASTR+o4]=hi;
            *(uint2*)&Alo[c*FASTR+o4]=lo;
        }
        #pragma unroll
        for(int i=0;i<8;i++){
            int idx=i*256+t; int c=idx>>5, y4=(idx&31)*4;
            uint2 hi=make_uint2(0,0), lo=make_uint2(0,0);
            if(y4<120) split4(*(const float4*)(srow+(size_t)(kc*64+c)*NP*NP+y4),hi,lo);
            *(uint2*)&Bhi[c*FBSTR+y4]=hi;
            *(uint2*)&Blo[c*FBSTR+y4]=lo;
        }
        __syncthreads();
        #pragma unroll
        for(int kk=0;kk<4;kk++){
            uint32_t a[4][4];
            #pragma unroll
            for(int mi=0;mi<4;mi++){
                uint32_t off=(uint32_t)((kk*16+ktr)*(2*FASTR)+(wm+mi*16)*2)+mcolb;
                ldmx4t(a[mi], AhiB+off);
            }
            uint32_t bh[4][2], bl[4][2];
            #pragma unroll
            for(int ni=0;ni<4;ni++){
                uint32_t off=(uint32_t)((kk*16+arow)*(2*FBSTR)+(wn+ni*8)*2);
                ldmx2t(bh[ni], BhiB+off);
                ldmx2t(bl[ni], BloB+off);
            }
            #pragma unroll
            for(int mi=0;mi<4;mi++)
                #pragma unroll
                for(int ni=0;ni<4;ni++){
                    mma_bf16(acc[mi][ni], a[mi], bh[ni]);
                    mma_bf16(acc[mi][ni], a[mi], bl[ni]);
                }
            #pragma unroll
            for(int mi=0;mi<4;mi++){
                uint32_t off=(uint32_t)((kk*16+ktr)*(2*FASTR)+(wm+mi*16)*2)+mcolb;
                ldmx4t(a[mi], AloB+off);
            }
            #pragma unroll
            for(int mi=0;mi<4;mi++)
                #pragma unroll
                for(int ni=0;ni<4;ni++)
                    mma_bf16(acc[mi][ni], a[mi], bh[ni]);
        }
        __syncthreads();
    }

    int r0=lane>>2, c0=(lane&3)*2;
    #pragma unroll
    for(int mi=0;mi<4;mi++){
        int o0=wm+mi*16+r0, o1=o0+8;
        float b0=__ldg(b+o0), b1v=__ldg(b+o1);
        #pragma unroll
        for(int ni=0;ni<4;ni++){
            int col=wn+ni*8+c0;
            if(col<120){
                *(float2*)&g_feat[(size_t)o0*NPOS+pbase+col]=
                    make_float2(gelu_f(acc[mi][ni][0]+b0), gelu_f(acc[mi][ni][1]+b0));
                *(float2*)&g_feat[(size_t)o1*NPOS+pbase+col]=
                    make_float2(gelu_f(acc[mi][ni][2]+b1v), gelu_f(acc[mi][ni][3]+b1v));
            }
        }
    }
}

// ---- 4 heads via mma ----
__global__ void __launch_bounds__(256,2) k_heads_mma(const float* __restrict__ w1,
                                                     const float* __restrict__ b1,
                                                     const float* __restrict__ w2,
                                                     const float* __restrict__ b2,
                                                     float* __restrict__ out){
    extern __shared__ __nv_bfloat16 smH[];
    __nv_bfloat16* Bhi = smH;
    __nv_bfloat16* Blo = Bhi + 128*FBSTR;
    __nv_bfloat16* Ahi = Blo + 128*FBSTR;
    __nv_bfloat16* Alo = Ahi + 128*HASTR;
    int t=threadIdx.x, lane=t&31, wid=t>>5;
    int pbase=blockIdx.x*128;
    uint32_t AhiB=smem_u32(Ahi), AloB=smem_u32(Alo);
    uint32_t BhiB=smem_u32(Bhi), BloB=smem_u32(Blo);
    int arow=lane&15;
    int ktr=(lane&7)+((lane>>4)<<3);
    uint32_t mcolb=(uint32_t)(((lane>>3)&1)<<4);
    int wn=wid*16;

    #pragma unroll
    for(int i=0;i<16;i++){
        int idx=i*256+t; int c=idx>>5, p4=(idx&31)*4;
        uint2 hi,lo; split4(*(const float4*)(g_feat+(size_t)c*NPOS+pbase+p4),hi,lo);
        *(uint2*)&Bhi[c*FBSTR+p4]=hi;
        *(uint2*)&Blo[c*FBSTR+p4]=lo;
    }

    for(int k=0;k<4;k++){
        #pragma unroll
        for(int i=0;i<8;i++){
            int idx=i*256+t; int c=idx>>4, d4=(idx&15)*4;
            uint2 hi,lo; split4(*(const float4*)(w1+(size_t)k*CH*64+(size_t)c*64+d4),hi,lo);
            *(uint2*)&Ahi[c*HASTR+d4]=hi;
            *(uint2*)&Alo[c*HASTR+d4]=lo;
        }
        __syncthreads();

        float acc[4][2][4];
        #pragma unroll
        for(int mi=0;mi<4;mi++)
            #pragma unroll
            for(int ni=0;ni<2;ni++){
                acc[mi][ni][0]=0.f; acc[mi][ni][1]=0.f;
                acc[mi][ni][2]=0.f; acc[mi][ni][3]=0.f;
            }
        #pragma unroll
        for(int kk=0;kk<8;kk++){
            uint32_t a[4][4];
            #pragma unroll
            for(int mi=0;mi<4;mi++){
                uint32_t off=(uint32_t)((kk*16+ktr)*(2*HASTR)+(mi*16)*2)+mcolb;
                ldmx4t(a[mi], AhiB+off);
            }
            uint32_t bh[2][2], bl[2][2];
            #pragma unroll
            for(int ni=0;ni<2;ni++){
                uint32_t off=(uint32_t)((kk*16+arow)*(2*FBSTR)+(wn+ni*8)*2);
                ldmx2t(bh[ni], BhiB+off);
                ldmx2t(bl[ni], BloB+off);
            }
            #pragma unroll
            for(int mi=0;mi<4;mi++)
                #pragma unroll
                for(int ni=0;ni<2;ni++){
                    mma_bf16(acc[mi][ni], a[mi], bh[ni]);
                    mma_bf16(acc[mi][ni], a[mi], bl[ni]);
                }
            #pragma unroll
            for(int mi=0;mi<4;mi++){
                uint32_t off=(uint32_t)((kk*16+ktr)*(2*HASTR)+(mi*16)*2)+mcolb;
                ldmx4t(a[mi], AloB+off);
            }
            #pragma unroll
            for(int mi=0;mi<4;mi++)
                #pragma unroll
                for(int ni=0;ni<2;ni++)
                    mma_bf16(acc[mi][ni], a[mi], bh[ni]);
        }

        int r0=lane>>2;
        #pragma unroll
        for(int ni=0;ni<2;ni++){
            float s0=0.f, s1=0.f;
            #pragma unroll
            for(int mi=0;mi<4;mi++){
                int d0=mi*16+r0, d1=d0+8;
                float w0=__ldg(w2+k*64+d0), w1v=__ldg(w2+k*64+d1);
                float bb0=__ldg(b1+k*64+d0), bb1=__ldg(b1+k*64+d1);
                s0=fmaf(gelu_f(acc[mi][ni][0]+bb0),w0,s0);
                s0=fmaf(gelu_f(acc[mi][ni][2]+bb1),w1v,s0);
                s1=fmaf(gelu_f(acc[mi][ni][1]+bb0),w0,s1);
                s1=fmaf(gelu_f(acc[mi][ni][3]+bb1),w1v,s1);
            }
            #pragma unroll
            for(int m=4;m<=16;m<<=1){
                s0+=__shfl_xor_sync(0xFFFFFFFFu,s0,m);
                s1+=__shfl_xor_sync(0xFFFFFFFFu,s1,m);
            }
            if((lane>>2)==0){
                int p=pbase+wn+ni*8+(lane&3)*2;
                float bk=__ldg(b2+k);
                out[(size_t)k*NPOS+p  ]=s0+bk;
                out[(size_t)k*NPOS+p+1]=s1+bk;
            }
        }
        __syncthreads();
    }
}

extern "C" void kernel_launch(void* const* d_in, const int* in_sizes, int n_in,
                              void* d_out, int out_size){
    (void)in_sizes; (void)n_in; (void)out_size;
    const float* x     =(const float*)d_in[0];
    const float* fc0_w =(const float*)d_in[1];
    const float* fc0_b =(const float*)d_in[2];
    const float* sw1   =(const float*)d_in[3];
    const float* sw2   =(const float*)d_in[4];
    const float* w_w   =(const float*)d_in[5];
    const float* w_b   =(const float*)d_in[6];
    const float* fc1_w =(const float*)d_in[7];
    const float* fc1_b =(const float*)d_in[8];
    const float* h1w   =(const float*)d_in[9];
    const float* h1b   =(const float*)d_in[10];
    const float* h2w   =(const float*)d_in[11];
    const float* h2b   =(const float*)d_in[12];
    float* out=(float*)d_out;

    const int LIN_SMEM = (2*128*ASTR + 2*64*BSTR)*2;            // 71680
    const int DFT_SMEM = (2*128*DASTR + 2*64*DBSTR)*2;          // 51200
    const int FC1_SMEM = (2*64*FASTR + 2*64*FBSTR)*2;           // 69632
    const int HED_SMEM = (2*128*FBSTR + 2*128*HASTR)*2;         // 106496
    cudaFuncSetAttribute(k_lin_mma,   cudaFuncAttributeMaxDynamicSharedMemorySize, LIN_SMEM);
    cudaFuncSetAttribute(k_dfty_mma,  cudaFuncAttributeMaxDynamicSharedMemorySize, DFT_SMEM);
    cudaFuncSetAttribute(k_fc1_mma,   cudaFuncAttributeMaxDynamicSharedMemorySize, FC1_SMEM);
    cudaFuncSetAttribute(k_heads_mma, cudaFuncAttributeMaxDynamicSharedMemorySize, HED_SMEM);

    k_tables<<<40,256>>>();
    k_packtw<<<48,256>>>();
    k_fc0<<<dim3(NP,NB),256>>>(x,fc0_w,fc0_b);
    for(int l=0;l<5;l++){
        int pp=l&1;
        k_dfty_mma <<<512,256,DFT_SMEM>>>(pp);
        k_dftx <<<NB*CH,800>>>();
        k_mix  <<<dim3(KXN,5),1024>>>(sw1,sw2,l);
        k_idftx<<<NB*CH,512>>>();
        k_lin_mma<<<dim3(512,1,NB),256,LIN_SMEM>>>(pp,w_w,w_b,l,(l<4)?1:0);
    }
    k_fc1_mma  <<<960,256,FC1_SMEM>>>(fc1_w,fc1_b);
    k_heads_mma<<<900,256,HED_SMEM>>>(h1w,h1b,h2w,h2b,out);
}

// round 16
// speedup vs baseline: 2.2425x; 1.1002x over previous
#include <cuda_runtime.h>
#include <cuda_bf16.h>
#include <math.h>
#include <stdint.h>

#define NB 2
#define CH 128
#define NP 256
#define SS 240
#define MM 20
#define KXN 40
#define NPIX (SS*SS)
#define NPOS (NB*NPIX)
#define ASTR 72    // k_lin A row stride (bf16)
#define BSTR 136   // k_lin B row stride (bf16)
#define DASTR 72   // dfty A stride
#define DBSTR 56   // dfty B stride
#define FASTR 136  // fc1 A ([c][o]) stride
#define FBSTR 136  // fc1/heads B stride
#define HASTR 72   // heads A ([c][d]) stride
#define XASTR 72   // dftx A chunk stride (64+8)
#define XBSTR 104  // dftx B stride (96+8)
#define IXASTR 88  // idftx A stride (80+8)
#define IXBSTR 136 // idftx B stride (128+8)

// ---- scratch (device globals; no allocation allowed) ----
__device__ float  g_hA[NB*CH*NP*NP];
__device__ float  g_hB[NB*CH*NP*NP];
__device__ float2 g_Gy [NB*CH*NP*MM];
__device__ float2 g_Fm [NB*CH*KXN*MM];
__device__ float2 g_Fo [NB*CH*KXN*MM];
__device__ float2 g_Gy2[NB*CH*NP*MM];
__device__ float  g_feat[CH*NPOS];   // [o][p] layout
__device__ __nv_bfloat16 g_Tf_hi[NP*48],  g_Tf_lo[NP*48];    // dfty  B: [y][n]
__device__ __nv_bfloat16 g_Ti_hi[48*NP],  g_Ti_lo[48*NP];    // lin-spec B: [k][y]
__device__ __nv_bfloat16 g_Txf_hi[512*96], g_Txf_lo[512*96]; // dftx B: [2x+ri][n]
__device__ __nv_bfloat16 g_Txi_hi[80*512], g_Txi_lo[80*512]; // idftx B: [2kxi+ri][2x+ro]

__device__ __forceinline__ float gelu_f(float v){
    return 0.5f*v*(1.0f+erff(v*0.70710678118654752f));
}

// ================= warp-mma helpers =================
__device__ __forceinline__ uint32_t smem_u32(const void* p){
    uint32_t a;
    asm("{ .reg .u64 t; cvta.to.shared.u64 t, %1; cvt.u32.u64 %0, t; }" : "=r"(a) : "l"(p));
    return a;
}
__device__ __forceinline__ void ldmx4(uint32_t* r, uint32_t addr){
    asm volatile("ldmatrix.sync.aligned.m8n8.x4.shared.b16 {%0,%1,%2,%3}, [%4];"
        : "=r"(r[0]),"=r"(r[1]),"=r"(r[2]),"=r"(r[3]) : "r"(addr));
}
__device__ __forceinline__ void ldmx4t(uint32_t* r, uint32_t addr){
    asm volatile("ldmatrix.sync.aligned.m8n8.x4.trans.shared.b16 {%0,%1,%2,%3}, [%4];"
        : "=r"(r[0]),"=r"(r[1]),"=r"(r[2]),"=r"(r[3]) : "r"(addr));
}
__device__ __forceinline__ void ldmx2t(uint32_t* r, uint32_t addr){
    asm volatile("ldmatrix.sync.aligned.m8n8.x2.trans.shared.b16 {%0,%1}, [%2];"
        : "=r"(r[0]),"=r"(r[1]) : "r"(addr));
}
__device__ __forceinline__ void mma_bf16(float* c, const uint32_t* a, const uint32_t* b){
    asm volatile("mma.sync.aligned.m16n8k16.row.col.f32.bf16.bf16.f32 "
        "{%0,%1,%2,%3}, {%4,%5,%6,%7}, {%8,%9}, {%0,%1,%2,%3};"
        : "+f"(c[0]),"+f"(c[1]),"+f"(c[2]),"+f"(c[3])
        : "r"(a[0]),"r"(a[1]),"r"(a[2]),"r"(a[3]), "r"(b[0]),"r"(b[1]));
}
__device__ __forceinline__ uint32_t pkbf2(float lo, float hi){
    uint32_t r; asm("cvt.rn.bf16x2.f32 %0, %1, %2;" : "=r"(r) : "f"(hi), "f"(lo)); return r;
}
__device__ __forceinline__ void split4(float4 v, uint2& hi, uint2& lo){
    uint32_t h0=pkbf2(v.x,v.y), h1=pkbf2(v.z,v.w);
    float r0=v.x-__uint_as_float(h0<<16);
    float r1=v.y-__uint_as_float(h0&0xFFFF0000u);
    float r2=v.z-__uint_as_float(h1<<16);
    float r3=v.w-__uint_as_float(h1&0xFFFF0000u);
    hi=make_uint2(h0,h1); lo=make_uint2(pkbf2(r0,r1),pkbf2(r2,r3));
}
__device__ __forceinline__ void split2(float a, float b, uint32_t& hi, uint32_t& lo){
    hi=pkbf2(a,b);
    float r0=a-__uint_as_float(hi<<16);
    float r1=b-__uint_as_float(hi&0xFFFF0000u);
    lo=pkbf2(r0,r1);
}

// ---- twiddle tables ----
__global__ void k_packtw(){
    int n=blockIdx.x, y=threadIdx.x;
    float v=0.f;
    if(n<40){
        int ky=n>>1;
        float s,c; sincospif((float)(ky*y)*(1.0f/128.0f), &s, &c);
        v = (n&1)? -s : c;
    }
    __nv_bfloat16 hi=__float2bfloat16(v);
    __nv_bfloat16 lo=__float2bfloat16(v-__bfloat162float(hi));
    g_Tf_hi[y*48+n]=hi; g_Tf_lo[y*48+n]=lo;
    g_Ti_hi[n*NP+y]=hi; g_Ti_lo[n*NP+y]=lo;
}
// dftx B: k=2x+ri, n<40: Fre col (kxi=n): v= ri? s:c ; n in[40,80): Fim col: v= ri? c:-s
__global__ void k_packtxf(){
    int k=blockIdx.x, n=threadIdx.x;      // k 0..511, n 0..95
    int x=k>>1, ri=k&1;
    float v=0.f;
    if(n<80){
        int kxi=(n<40)? n : n-40;
        int kx=(kxi<MM)? kxi : 236+(kxi-MM);
        float s,c; sincospif((float)(kx*x)*(1.0f/128.0f), &s, &c);
        v = (n<40) ? (ri? s : c) : (ri? c : -s);
    }
    __nv_bfloat16 hi=__float2bfloat16(v);
    __nv_bfloat16 lo=__float2bfloat16(v-__bfloat162float(hi));
    g_Txf_hi[k*96+n]=hi; g_Txf_lo[k*96+n]=lo;
}
// idftx B: k=2kxi+ri, n=2x+ro: ro=0: v= ri? -s:c ; ro=1: v= ri? c:s
__global__ void k_packtxi(){
    int k=blockIdx.x, n=threadIdx.x;      // k 0..79, n 0..511
    int kxi=k>>1, ri=k&1;
    int x=n>>1, ro=n&1;
    int kx=(kxi<MM)? kxi : 236+(kxi-MM);
    float s,c; sincospif((float)(kx*x)*(1.0f/128.0f), &s, &c);
    float v = (ro==0) ? (ri? -s : c) : (ri? c : s);
    __nv_bfloat16 hi=__float2bfloat16(v);
    __nv_bfloat16 lo=__float2bfloat16(v-__bfloat162float(hi));
    g_Txi_hi[k*512+n]=hi; g_Txi_lo[k*512+n]=lo;
}

// ---- fc0 + grid channels, write padded (b,c,x,y) into g_hA ----
__global__ void k_fc0(const float* __restrict__ x, const float* __restrict__ w,
                      const float* __restrict__ b){
    __shared__ float ws[5][CH];
    __shared__ float bs[CH];
    int t=threadIdx.x;
    for(int i=t;i<5*CH;i+=256) ws[i/CH][i%CH]=w[i];
    for(int i=t;i<CH;i+=256) bs[i]=b[i];
    __syncthreads();
    int xr=blockIdx.x, bb=blockIdx.y, y=t;
    bool inside=(xr<SS)&&(y<SS);
    float v0=0.f,v1=0.f,v2=0.f,v3=0.f,v4=0.f;
    if(inside){
        const float* xp=x+(((size_t)bb*SS+xr)*SS+y)*3;
        v0=xp[0]; v1=xp[1]; v2=xp[2];
        v3=(float)xr*(1.0f/239.0f);
        v4=(float)y *(1.0f/239.0f);
    }
    float* op=g_hA+(((size_t)bb*CH)*NP+xr)*NP+y;
    for(int c=0;c<CH;c++){
        float a=0.f;
        if(inside){
            a=bs[c];
            a=fmaf(v0,ws[0][c],a); a=fmaf(v1,ws[1][c],a); a=fmaf(v2,ws[2][c],a);
            a=fmaf(v3,ws[3][c],a); a=fmaf(v4,ws[4][c],a);
        }
        op[(size_t)c*NP*NP]=a;
    }
}

// ---- forward y-DFT via mma ----
__global__ void __launch_bounds__(256,2) k_dfty_mma(int pp){
    extern __shared__ __nv_bfloat16 smD[];
    __nv_bfloat16* Ahi=smD;
    __nv_bfloat16* Alo=Ahi+128*DASTR;
    __nv_bfloat16* Bhi=Alo+128*DASTR;
    __nv_bfloat16* Blo=Bhi+64*DBSTR;
    const float* h = pp? g_hB : g_hA;
    int t=threadIdx.x, lane=t&31, wid=t>>5;
    size_t rowbase=(size_t)blockIdx.x*128;
    const float* srow = h + rowbase*NP;
    float acc[6][4];
    #pragma unroll
    for(int ni=0;ni<6;ni++){ acc[ni][0]=0.f; acc[ni][1]=0.f; acc[ni][2]=0.f; acc[ni][3]=0.f; }
    uint32_t AhiB=smem_u32(Ahi), AloB=smem_u32(Alo);
    uint32_t BhiB=smem_u32(Bhi), BloB=smem_u32(Blo);
    int arow=lane&15;
    uint32_t acolb=(uint32_t)((lane>>4)<<4);
    int wm=wid*16;

    for(int kc=0;kc<4;kc++){
        #pragma unroll
        for(int i=0;i<8;i++){
            int idx=i*256+t; int r=idx>>4, c4=(idx&15)*4;
            uint2 hi,lo; split4(*(const float4*)(srow+(size_t)r*NP+kc*64+c4),hi,lo);
            *(uint2*)&Ahi[r*DASTR+c4]=hi;
            *(uint2*)&Alo[r*DASTR+c4]=lo;
        }
        #pragma unroll
        for(int i=0;i<6;i++){
            int idx=i*256+t; int k=idx/24, n2=(idx%24)*2;
            *(uint32_t*)&Bhi[k*DBSTR+n2]=*(const uint32_t*)&g_Tf_hi[(kc*64+k)*48+n2];
            *(uint32_t*)&Blo[k*DBSTR+n2]=*(const uint32_t*)&g_Tf_lo[(kc*64+k)*48+n2];
        }
        __syncthreads();
        #pragma unroll
        for(int kk=0;kk<4;kk++){
            uint32_t a[4];
            uint32_t aoff=(uint32_t)((wm+arow)*(2*DASTR)+kk*32)+acolb;
            ldmx4(a, AhiB+aoff);
            uint32_t bh[6][2], bl[6][2];
            #pragma unroll
            for(int ni=0;ni<6;ni++){
                uint32_t off=(uint32_t)((kk*16+arow)*(2*DBSTR)+ni*16);
                ldmx2t(bh[ni], BhiB+off);
                ldmx2t(bl[ni], BloB+off);
            }
            #pragma unroll
            for(int ni=0;ni<6;ni++){
                mma_bf16(acc[ni], a, bh[ni]);
                mma_bf16(acc[ni], a, bl[ni]);
            }
            uint32_t a2[4];
            ldmx4(a2, AloB+aoff);
            #pragma unroll
            for(int ni=0;ni<6;ni++)
                mma_bf16(acc[ni], a2, bh[ni]);
        }
        __syncthreads();
    }
    int r0=lane>>2, cq=lane&3;
    #pragma unroll
    for(int ni=0;ni<5;ni++){
        int ky=ni*4+cq;
        g_Gy[(rowbase+wm+r0  )*MM+ky]=make_float2(acc[ni][0],acc[ni][1]);
        g_Gy[(rowbase+wm+r0+8)*MM+ky]=make_float2(acc[ni][2],acc[ni][3]);
    }
}

// ---- forward x-DFT via mma: rows=(bc,ky) 5120, K=512 (x,ri), N=96 (re40|im40|pad) ----
__global__ void __launch_bounds__(256,2) k_dftx_mma(){
    extern __shared__ __nv_bfloat16 smX[];
    __nv_bfloat16* Ahi=smX;                   // [128][XASTR]
    __nv_bfloat16* Alo=Ahi+128*XASTR;
    __nv_bfloat16* Bhi=Alo+128*XASTR;         // [64][XBSTR]
    __nv_bfloat16* Blo=Bhi+64*XBSTR;
    int t=threadIdx.x, lane=t&31, wid=t>>5;
    int rowbase=blockIdx.x*128;
    int wm=(wid>>2)*64, wn=(wid&3)*24;
    float acc[4][3][4];
    #pragma unroll
    for(int mi=0;mi<4;mi++)
        #pragma unroll
        for(int ni=0;ni<3;ni++){
            acc[mi][ni][0]=0.f; acc[mi][ni][1]=0.f;
            acc[mi][ni][2]=0.f; acc[mi][ni][3]=0.f;
        }
    uint32_t AhiB=smem_u32(Ahi), AloB=smem_u32(Alo);
    uint32_t BhiB=smem_u32(Bhi), BloB=smem_u32(Blo);
    int arow=lane&15;
    uint32_t acolb=(uint32_t)((lane>>4)<<4);

    for(int kc=0;kc<8;kc++){
        #pragma unroll
        for(int i=0;i<16;i++){                // A: 128 rows x 32 x-pairs
            int idx=i*256+t; int r=idx&127, xl=idx>>7;
            int R=rowbase+r; int bc=R/20, ky=R-bc*20;
            float2 g=g_Gy[((size_t)bc*NP + kc*32+xl)*MM + ky];
            uint32_t hi,lo; split2(g.x,g.y,hi,lo);
            *(uint32_t*)&Ahi[r*XASTR+2*xl]=hi;
            *(uint32_t*)&Alo[r*XASTR+2*xl]=lo;
        }
        #pragma unroll
        for(int i=0;i<6;i++){                 // B: 64 k x 96 n
            int idx=i*256+t; int k=idx/24, n4=(idx%24)*4;
            *(uint2*)&Bhi[k*XBSTR+n4]=*(const uint2*)&g_Txf_hi[(kc*64+k)*96+n4];
            *(uint2*)&Blo[k*XBSTR+n4]=*(const uint2*)&g_Txf_lo[(kc*64+k)*96+n4];
        }
        __syncthreads();
        #pragma unroll
        for(int kk=0;kk<4;kk++){
            uint32_t a[4][4];
            #pragma unroll
            for(int mi=0;mi<4;mi++){
                uint32_t off=(uint32_t)((wm+mi*16+arow)*(2*XASTR)+kk*32)+acolb;
                ldmx4(a[mi], AhiB+off);
            }
            uint32_t bh[3][2], bl[3][2];
            #pragma unroll
            for(int ni=0;ni<3;ni++){
                uint32_t off=(uint32_t)((kk*16+arow)*(2*XBSTR)+(wn+ni*8)*2);
                ldmx2t(bh[ni], BhiB+off);
                ldmx2t(bl[ni], BloB+off);
            }
            #pragma unroll
            for(int mi=0;mi<4;mi++)
                #pragma unroll
                for(int ni=0;ni<3;ni++){
                    mma_bf16(acc[mi][ni], a[mi], bh[ni]);
                    mma_bf16(acc[mi][ni], a[mi], bl[ni]);
                }
            #pragma unroll
            for(int mi=0;mi<4;mi++){
                uint32_t off=(uint32_t)((wm+mi*16+arow)*(2*XASTR)+kk*32)+acolb;
                ldmx4(a[mi], AloB+off);
            }
            #pragma unroll
            for(int mi=0;mi<4;mi++)
                #pragma unroll
                for(int ni=0;ni<3;ni++)
                    mma_bf16(acc[mi][ni], a[mi], bh[ni]);
        }
        __syncthreads();
    }

    int r0=lane>>2, c0=(lane&3)*2;
    float* fmf=(float*)g_Fm;
    #pragma unroll
    for(int mi=0;mi<4;mi++){
        int R0=rowbase+wm+mi*16+r0, R1=R0+8;
        int bc0=R0/20, ky0=R0-bc0*20;
        int bc1=R1/20, ky1=R1-bc1*20;
        #pragma unroll
        for(int ni=0;ni<3;ni++){
            int n=wn+ni*8+c0;
            if(n<80){
                int ri=(n>=40)?1:0;
                int kxi=n-ri*40;
                size_t b0=(((size_t)bc0*KXN+kxi)*MM+ky0)*2+ri;
                size_t b1=(((size_t)bc1*KXN+kxi)*MM+ky1)*2+ri;
                fmf[b0]     =acc[mi][ni][0];
                fmf[b0+2*MM]=acc[mi][ni][1];   // kxi+1
                fmf[b1]     =acc[mi][ni][2];
                fmf[b1+2*MM]=acc[mi][ni][3];
            }
        }
    }
}

// ---- mode mixing ----
__global__ void __launch_bounds__(1024) k_mix(const float* __restrict__ w1,
                                              const float* __restrict__ w2, int l){
    __shared__ float2 fsh[2][CH][4];
    int kxi=blockIdx.x, myg=blockIdx.y, t=threadIdx.x;
    {
        int b=t>>9, rem=t&511, i=rem>>2, myl=rem&3;
        fsh[b][i][myl]=g_Fm[(((size_t)(b*CH+i))*KXN+kxi)*MM + myg*4+myl];
    }
    __syncthreads();
    int myl=t&3, b=(t>>2)&1, o=t>>3;
    int my=myg*4+myl;
    int mx=(kxi<MM)? kxi : (kxi-MM);
    const float2* wp=(const float2*)((kxi<MM)? w1 : w2);
    size_t base=(((size_t)l*CH*CH + o)*MM + mx)*MM + my;
    float ar=0.f, ai=0.f;
    #pragma unroll 4
    for(int i=0;i<CH;i++){
        float2 wv=wp[base+(size_t)i*CH*MM*MM];
        float2 f=fsh[b][i][myl];
        ar += f.x*wv.x - f.y*wv.y;
        ai += f.x*wv.y + f.y*wv.x;
    }
    g_Fo[(((size_t)(b*CH+o))*KXN+kxi)*MM+my]=make_float2(ar,ai);
}

// ---- inverse x-DFT via mma: rows=(bc,ky) 5120, K=80 (kxi,ri), N=512 via grid.y ----
__global__ void __launch_bounds__(256,2) k_idftx_mma(){
    extern __shared__ __nv_bfloat16 smIX[];
    __nv_bfloat16* Ahi=smIX;                  // [128][IXASTR]
    __nv_bfloat16* Alo=Ahi+128*IXASTR;
    __nv_bfloat16* Bhi=Alo+128*IXASTR;        // [80][IXBSTR]
    __nv_bfloat16* Blo=Bhi+80*IXBSTR;
    int t=threadIdx.x, lane=t&31, wid=t>>5;
    int rowbase=blockIdx.x*128;
    int nbase=blockIdx.y*128;
    int wm=(wid>>2)*64, wn=(wid&3)*32;
    uint32_t AhiB=smem_u32(Ahi), AloB=smem_u32(Alo);
    uint32_t BhiB=smem_u32(Bhi), BloB=smem_u32(Blo);
    int arow=lane&15;
    uint32_t acolb=(uint32_t)((lane>>4)<<4);

    #pragma unroll
    for(int i=0;i<20;i++){                    // A: 128 rows x 40 kxi, scaled by fk(ky)
        int idx=i*256+t; int r=idx&127, kxi=idx>>7;
        int R=rowbase+r; int bc=R/20, ky=R-bc*20;
        float2 f=g_Fo[((size_t)bc*KXN+kxi)*MM+ky];
        float fk=((ky==0)?1.0f:2.0f)*(1.0f/65536.0f);
        uint32_t hi,lo; split2(f.x*fk,f.y*fk,hi,lo);
        *(uint32_t*)&Ahi[r*IXASTR+2*kxi]=hi;
        *(uint32_t*)&Alo[r*IXASTR+2*kxi]=lo;
    }
    #pragma unroll
    for(int i=0;i<10;i++){                    // B: 80 k x 128 n
        int idx=i*256+t; int k=idx/32, n4=(idx%32)*4;
        *(uint2*)&Bhi[k*IXBSTR+n4]=*(const uint2*)&g_Txi_hi[k*512+nbase+n4];
        *(uint2*)&Blo[k*IXBSTR+n4]=*(const uint2*)&g_Txi_lo[k*512+nbase+n4];
    }
    __syncthreads();

    float acc[4][4][4];
    #pragma unroll
    for(int mi=0;mi<4;mi++)
        #pragma unroll
        for(int ni=0;ni<4;ni++){
            acc[mi][ni][0]=0.f; acc[mi][ni][1]=0.f;
            acc[mi][ni][2]=0.f; acc[mi][ni][3]=0.f;
        }
    #pragma unroll
    for(int kk=0;kk<5;kk++){
        uint32_t a[4][4];
        #pragma unroll
        for(int mi=0;mi<4;mi++){
            uint32_t off=(uint32_t)((wm+mi*16+arow)*(2*IXASTR)+kk*32)+acolb;
            ldmx4(a[mi], AhiB+off);
        }
        uint32_t bh[4][2], bl[4][2];
        #pragma unroll
        for(int ni=0;ni<4;ni++){
            uint32_t off=(uint32_t)((kk*16+arow)*(2*IXBSTR)+(wn+ni*8)*2);
            ldmx2t(bh[ni], BhiB+off);
            ldmx2t(bl[ni], BloB+off);
        }
        #pragma unroll
        for(int mi=0;mi<4;mi++)
            #pragma unroll
            for(int ni=0;ni<4;ni++){
                mma_bf16(acc[mi][ni], a[mi], bh[ni]);
                mma_bf16(acc[mi][ni], a[mi], bl[ni]);
            }
        #pragma unroll
        for(int mi=0;mi<4;mi++){
            uint32_t off=(uint32_t)((wm+mi*16+arow)*(2*IXASTR)+kk*32)+acolb;
            ldmx4(a[mi], AloB+off);
        }
        #pragma unroll
        for(int mi=0;mi<4;mi++)
            #pragma unroll
            for(int ni=0;ni<4;ni++)
                mma_bf16(acc[mi][ni], a[mi], bh[ni]);
    }

    int r0=lane>>2, c0=(lane&3)*2;            // c0 even -> n even -> (re,im) pair
    #pragma unroll
    for(int mi=0;mi<4;mi++){
        int R0=rowbase+wm+mi*16+r0, R1=R0+8;
        int bc0=R0/20, ky0=R0-bc0*20;
        int bc1=R1/20, ky1=R1-bc1*20;
        #pragma unroll
        for(int ni=0;ni<4;ni++){
            int n=wn+ni*8+c0;
            int x=(nbase+n)>>1;
            g_Gy2[((size_t)bc0*NP+x)*MM+ky0]=make_float2(acc[mi][ni][0],acc[mi][ni][1]);
            g_Gy2[((size_t)bc1*NP+x)*MM+ky1]=make_float2(acc[mi][ni][2],acc[mi][ni][3]);
        }
    }
}

// ---- 1x1 conv + FUSED inverse y-DFT via mma (3 chunks: lin-k0, lin-k1, spec-K48) ----
__global__ void __launch_bounds__(256,2) k_lin_mma(int pp, const float* __restrict__ ww,
                                                   const float* __restrict__ wb, int l, int dogelu){
    extern __shared__ __nv_bfloat16 sm[];
    __nv_bfloat16* Ahi = sm;
    __nv_bfloat16* Alo = Ahi + 128*ASTR;
    __nv_bfloat16* Bhi = Alo + 128*ASTR;
    __nv_bfloat16* Blo = Bhi + 64*BSTR;
    const float* src = pp ? g_hB : g_hA;
    float*       dst = pp ? g_hA : g_hB;
    int t=threadIdx.x, lane=t&31, wid=t>>5;
    int x=blockIdx.x>>1, ybase=(blockIdx.x&1)<<7, bb=blockIdx.z;
    const float* W = ww + (size_t)l*CH*CH;
    const float* srow = src + (((size_t)bb*CH)*NP + x)*NP + ybase;

    int wm=(wid>>2)*64, wn=(wid&3)*32;
    float acc[4][4][4];
    #pragma unroll
    for(int mi=0;mi<4;mi++)
        #pragma unroll
        for(int ni=0;ni<4;ni++){
            acc[mi][ni][0]=0.f; acc[mi][ni][1]=0.f;
            acc[mi][ni][2]=0.f; acc[mi][ni][3]=0.f;
        }
    uint32_t AhiB=smem_u32(Ahi), AloB=smem_u32(Alo);
    uint32_t BhiB=smem_u32(Bhi), BloB=smem_u32(Blo);
    int arow=lane&15;
    uint32_t acolb=(uint32_t)((lane>>4)<<4);

    for(int kc=0;kc<3;kc++){
        if(kc<2){
            #pragma unroll
            for(int i=0;i<8;i++){
                int idx=i*256+t;
                int o=idx>>4, c4=(idx&15)*4;
                uint2 hi,lo; split4(*(const float4*)(W+(size_t)o*CH+kc*64+c4),hi,lo);
                *(uint2*)&Ahi[o*ASTR+c4]=hi;
                *(uint2*)&Alo[o*ASTR+c4]=lo;
            }
            #pragma unroll
            for(int i=0;i<8;i++){
                int idx=i*256+t;
                int c=idx>>5, y4=(idx&31)*4;
                uint2 hi,lo; split4(*(const float4*)(srow+(size_t)(kc*64+c)*NP*NP+y4),hi,lo);
                *(uint2*)&Bhi[c*BSTR+y4]=hi;
                *(uint2*)&Blo[c*BSTR+y4]=lo;
            }
        } else {
            #pragma unroll
            for(int i=0;i<5;i++){
                int idx=i*256+t; int r=idx/10, j4=(idx%10)*4;
                const float* gp=(const float*)g_Gy2 + (((size_t)(bb*CH+r))*NP + x)*2*MM;
                uint2 hi,lo; split4(*(const float4*)(gp+j4),hi,lo);
                *(uint2*)&Ahi[r*ASTR+j4]=hi;
                *(uint2*)&Alo[r*ASTR+j4]=lo;
            }
            #pragma unroll
            for(int i=0;i<4;i++){
                int idx=i*256+t; int r=idx>>3, c=idx&7;
                Ahi[r*ASTR+40+c]=__float2bfloat16(0.f);
                Alo[r*ASTR+40+c]=__float2bfloat16(0.f);
            }
            #pragma unroll
            for(int i=0;i<6;i++){
                int idx=i*256+t; int k=idx>>5, n4=(idx&31)*4;
                *(uint2*)&Bhi[k*BSTR+n4]=*(const uint2*)&g_Ti_hi[k*NP+ybase+n4];
                *(uint2*)&Blo[k*BSTR+n4]=*(const uint2*)&g_Ti_lo[k*NP+ybase+n4];
            }
        }
        __syncthreads();
        int kmax=(kc<2)?4:3;
        for(int kk=0;kk<kmax;kk++){
            uint32_t a[4][4];
            #pragma unroll
            for(int mi=0;mi<4;mi++){
                uint32_t off=(uint32_t)((wm+mi*16+arow)*(2*ASTR)+kk*32)+acolb;
                ldmx4(a[mi], AhiB+off);
            }
            uint32_t bh[4][2], bl[4][2];
            #pragma unroll
            for(int ni=0;ni<4;ni++){
                uint32_t off=(uint32_t)((kk*16+arow)*(2*BSTR)+(wn+ni*8)*2);
                ldmx2t(bh[ni], BhiB+off);
                ldmx2t(bl[ni], BloB+off);
            }
            #pragma unroll
            for(int mi=0;mi<4;mi++)
                #pragma unroll
                for(int ni=0;ni<4;ni++){
                    mma_bf16(acc[mi][ni], a[mi], bh[ni]);
                    mma_bf16(acc[mi][ni], a[mi], bl[ni]);
                }
            #pragma unroll
            for(int mi=0;mi<4;mi++){
                uint32_t off=(uint32_t)((wm+mi*16+arow)*(2*ASTR)+kk*32)+acolb;
                ldmx4(a[mi], AloB+off);
            }
            #pragma unroll
            for(int mi=0;mi<4;mi++)
                #pragma unroll
                for(int ni=0;ni<4;ni++)
                    mma_bf16(acc[mi][ni], a[mi], bh[ni]);
        }
        __syncthreads();
    }

    int r0=lane>>2, c0=(lane&3)*2;
    #pragma unroll
    for(int mi=0;mi<4;mi++){
        int o0=wm+mi*16+r0, o1=o0+8;
        float bias0=__ldg(wb+l*CH+o0), bias1=__ldg(wb+l*CH+o1);
        float* base0=dst+(((size_t)(bb*CH+o0))*NP+x)*NP+ybase;
        float* base1=dst+(((size_t)(bb*CH+o1))*NP+x)*NP+ybase;
        #pragma unroll
        for(int ni=0;ni<4;ni++){
            int y=wn+ni*8+c0;
            float2 v0=make_float2(acc[mi][ni][0]+bias0, acc[mi][ni][1]+bias0);
            float2 v1=make_float2(acc[mi][ni][2]+bias1, acc[mi][ni][3]+bias1);
            if(dogelu){
                v0.x=gelu_f(v0.x); v0.y=gelu_f(v0.y);
                v1.x=gelu_f(v1.x); v1.y=gelu_f(v1.y);
            }
            *(float2*)(base0+y)=v0;
            *(float2*)(base1+y)=v1;
        }
    }
}

// ---- fc1 via mma: feat[o][p] = gelu(W^T h + b) ----
__global__ void __launch_bounds__(256,2) k_fc1_mma(const float* __restrict__ w,
                                                   const float* __restrict__ b){
    extern __shared__ __nv_bfloat16 smF[];
    __nv_bfloat16* Ahi = smF;
    __nv_bfloat16* Alo = Ahi + 64*FASTR;
    __nv_bfloat16* Bhi = Alo + 64*FASTR;
    __nv_bfloat16* Blo = Bhi + 64*FBSTR;
    int t=threadIdx.x, lane=t&31, wid=t>>5;
    int bx=blockIdx.x;
    int bb=bx/480, rem=bx%480, xr=rem>>1, yh=rem&1;
    int pbase = bb*NPIX + xr*SS + yh*120;
    const float* srow = g_hB + (((size_t)bb*CH)*NP + xr)*NP + yh*120;

    int wm=(wid>>2)*64, wn=(wid&3)*32;
    float acc[4][4][4];
    #pragma unroll
    for(int mi=0;mi<4;mi++)
        #pragma unroll
        for(int ni=0;ni<4;ni++){
            acc[mi][ni][0]=0.f; acc[mi][ni][1]=0.f;
            acc[mi][ni][2]=0.f; acc[mi][ni][3]=0.f;
        }
    uint32_t AhiB=smem_u32(Ahi), AloB=smem_u32(Alo);
    uint32_t BhiB=smem_u32(Bhi), BloB=smem_u32(Blo);
    int arow=lane&15;
    int ktr=(lane&7)+((lane>>4)<<3);
    uint32_t mcolb=(uint32_t)(((lane>>3)&1)<<4);

    for(int kc=0;kc<2;kc++){
        #pragma unroll
        for(int i=0;i<8;i++){
            int idx=i*256+t; int c=idx>>5, o4=(idx&31)*4;
            uint2 hi,lo; split4(*(const float4*)(w+(size_t)(kc*64+c)*CH+o4),hi,lo);
            *(uint2*)&Ahi[c*FASTR+o4]=hi;
            *(uint2*)&Alo[c*FASTR+o4]=lo;
        }
        #pragma unroll
        for(int i=0;i<8;i++){
            int idx=i*256+t; int c=idx>>5, y4=(idx&31)*4;
            uint2 hi=make_uint2(0,0), lo=make_uint2(0,0);
            if(y4<120) split4(*(const float4*)(srow+(size_t)(kc*64+c)*NP*NP+y4),hi,lo);
            *(uint2*)&Bhi[c*FBSTR+y4]=hi;
            *(uint2*)&Blo[c*FBSTR+y4]=lo;
        }
        __syncthreads();
        #pragma unroll
        for(int kk=0;kk<4;kk++){
            uint32_t a[4][4];
            #pragma unroll
            for(int mi=0;mi<4;mi++){
                uint32_t off=(uint32_t)((kk*16+ktr)*(2*FASTR)+(wm+mi*16)*2)+mcolb;
                ldmx4t(a[mi], AhiB+off);
            }
            uint32_t bh[4][2], bl[4][2];
            #pragma unroll
            for(int ni=0;ni<4;ni++){
                uint32_t off=(uint32_t)((kk*16+arow)*(2*FBSTR)+(wn+ni*8)*2);
                ldmx2t(bh[ni], BhiB+off);
                ldmx2t(bl[ni], BloB+off);
            }
            #pragma unroll
            for(int mi=0;mi<4;mi++)
                #pragma unroll
                for(int ni=0;ni<4;ni++){
                    mma_bf16(acc[mi][ni], a[mi], bh[ni]);
                    mma_bf16(acc[mi][ni], a[mi], bl[ni]);
                }
            #pragma unroll
            for(int mi=0;mi<4;mi++){
                uint32_t off=(uint32_t)((kk*16+ktr)*(2*FASTR)+(wm+mi*16)*2)+mcolb;
                ldmx4t(a[mi], AloB+off);
            }
            #pragma unroll
            for(int mi=0;mi<4;mi++)
                #pragma unroll
                for(int ni=0;ni<4;ni++)
                    mma_bf16(acc[mi][ni], a[mi], bh[ni]);
        }
        __syncthreads();
    }

    int r0=lane>>2, c0=(lane&3)*2;
    #pragma unroll
    for(int mi=0;mi<4;mi++){
        int o0=wm+mi*16+r0, o1=o0+8;
        float b0=__ldg(b+o0), b1v=__ldg(b+o1);
        #pragma unroll
        for(int ni=0;ni<4;ni++){
            int col=wn+ni*8+c0;
            if(col<120){
                *(float2*)&g_feat[(size_t)o0*NPOS+pbase+col]=
                    make_float2(gelu_f(acc[mi][ni][0]+b0), gelu_f(acc[mi][ni][1]+b0));
                *(float2*)&g_feat[(size_t)o1*NPOS+pbase+col]=
                    make_float2(gelu_f(acc[mi][ni][2]+b1v), gelu_f(acc[mi][ni][3]+b1v));
            }
        }
    }
}

// ---- 4 heads via mma ----
__global__ void __launch_bounds__(256,2) k_heads_mma(const float* __restrict__ w1,
                                                     const float* __restrict__ b1,
                                                     const float* __restrict__ w2,
                                                     const float* __restrict__ b2,
                                                     float* __restrict__ out){
    extern __shared__ __nv_bfloat16 smH[];
    __nv_bfloat16* Bhi = smH;
    __nv_bfloat16* Blo = Bhi + 128*FBSTR;
    __nv_bfloat16* Ahi = Blo + 128*FBSTR;
    __nv_bfloat16* Alo = Ahi + 128*HASTR;
    int t=threadIdx.x, lane=t&31, wid=t>>5;
    int pbase=blockIdx.x*128;
    uint32_t AhiB=smem_u32(Ahi), AloB=smem_u32(Alo);
    uint32_t BhiB=smem_u32(Bhi), BloB=smem_u32(Blo);
    int arow=lane&15;
    int ktr=(lane&7)+((lane>>4)<<3);
    uint32_t mcolb=(uint32_t)(((lane>>3)&1)<<4);
    int wn=wid*16;

    #pragma unroll
    for(int i=0;i<16;i++){
        int idx=i*256+t; int c=idx>>5, p4=(idx&31)*4;
        uint2 hi,lo; split4(*(const float4*)(g_feat+(size_t)c*NPOS+pbase+p4),hi,lo);
        *(uint2*)&Bhi[c*FBSTR+p4]=hi;
        *(uint2*)&Blo[c*FBSTR+p4]=lo;
    }

    for(int k=0;k<4;k++){
        #pragma unroll
        for(int i=0;i<8;i++){
            int idx=i*256+t; int c=idx>>4, d4=(idx&15)*4;
            uint2 hi,lo; split4(*(const float4*)(w1+(size_t)k*CH*64+(size_t)c*64+d4),hi,lo);
            *(uint2*)&Ahi[c*HASTR+d4]=hi;
            *(uint2*)&Alo[c*HASTR+d4]=lo;
        }
        __syncthreads();

        float acc[4][2][4];
        #pragma unroll
        for(int mi=0;mi<4;mi++)
            #pragma unroll
            for(int ni=0;ni<2;ni++){
                acc[mi][ni][0]=0.f; acc[mi][ni][1]=0.f;
                acc[mi][ni][2]=0.f; acc[mi][ni][3]=0.f;
            }
        #pragma unroll
        for(int kk=0;kk<8;kk++){
            uint32_t a[4][4];
            #pragma unroll
            for(int mi=0;mi<4;mi++){
                uint32_t off=(uint32_t)((kk*16+ktr)*(2*HASTR)+(mi*16)*2)+mcolb;
                ldmx4t(a[mi], AhiB+off);
            }
            uint32_t bh[2][2], bl[2][2];
            #pragma unroll
            for(int ni=0;ni<2;ni++){
                uint32_t off=(uint32_t)((kk*16+arow)*(2*FBSTR)+(wn+ni*8)*2);
                ldmx2t(bh[ni], BhiB+off);
                ldmx2t(bl[ni], BloB+off);
            }
            #pragma unroll
            for(int mi=0;mi<4;mi++)
                #pragma unroll
                for(int ni=0;ni<2;ni++){
                    mma_bf16(acc[mi][ni], a[mi], bh[ni]);
                    mma_bf16(acc[mi][ni], a[mi], bl[ni]);
                }
            #pragma unroll
            for(int mi=0;mi<4;mi++){
                uint32_t off=(uint32_t)((kk*16+ktr)*(2*HASTR)+(mi*16)*2)+mcolb;
                ldmx4t(a[mi], AloB+off);
            }
            #pragma unroll
            for(int mi=0;mi<4;mi++)
                #pragma unroll
                for(int ni=0;ni<2;ni++)
                    mma_bf16(acc[mi][ni], a[mi], bh[ni]);
        }

        int r0=lane>>2;
        #pragma unroll
        for(int ni=0;ni<2;ni++){
            float s0=0.f, s1=0.f;
            #pragma unroll
            for(int mi=0;mi<4;mi++){
                int d0=mi*16+r0, d1=d0+8;
                float w0=__ldg(w2+k*64+d0), w1v=__ldg(w2+k*64+d1);
                float bb0=__ldg(b1+k*64+d0), bb1=__ldg(b1+k*64+d1);
                s0=fmaf(gelu_f(acc[mi][ni][0]+bb0),w0,s0);
                s0=fmaf(gelu_f(acc[mi][ni][2]+bb1),w1v,s0);
                s1=fmaf(gelu_f(acc[mi][ni][1]+bb0),w0,s1);
                s1=fmaf(gelu_f(acc[mi][ni][3]+bb1),w1v,s1);
            }
            #pragma unroll
            for(int m=4;m<=16;m<<=1){
                s0+=__shfl_xor_sync(0xFFFFFFFFu,s0,m);
                s1+=__shfl_xor_sync(0xFFFFFFFFu,s1,m);
            }
            if((lane>>2)==0){
                int p=pbase+wn+ni*8+(lane&3)*2;
                float bk=__ldg(b2+k);
                out[(size_t)k*NPOS+p  ]=s0+bk;
                out[(size_t)k*NPOS+p+1]=s1+bk;
            }
        }
        __syncthreads();
    }
}

extern "C" void kernel_launch(void* const* d_in, const int* in_sizes, int n_in,
                              void* d_out, int out_size){
    (void)in_sizes; (void)n_in; (void)out_size;
    const float* x     =(const float*)d_in[0];
    const float* fc0_w =(const float*)d_in[1];
    const float* fc0_b =(const float*)d_in[2];
    const float* sw1   =(const float*)d_in[3];
    const float* sw2   =(const float*)d_in[4];
    const float* w_w   =(const float*)d_in[5];
    const float* w_b   =(const float*)d_in[6];
    const float* fc1_w =(const float*)d_in[7];
    const float* fc1_b =(const float*)d_in[8];
    const float* h1w   =(const float*)d_in[9];
    const float* h1b   =(const float*)d_in[10];
    const float* h2w   =(const float*)d_in[11];
    const float* h2b   =(const float*)d_in[12];
    float* out=(float*)d_out;

    const int LIN_SMEM = (2*128*ASTR + 2*64*BSTR)*2;            // 71680
    const int DFT_SMEM = (2*128*DASTR + 2*64*DBSTR)*2;          // 51200
    const int FC1_SMEM = (2*64*FASTR + 2*64*FBSTR)*2;           // 69632
    const int HED_SMEM = (2*128*FBSTR + 2*128*HASTR)*2;         // 106496
    const int DX_SMEM  = (2*128*XASTR + 2*64*XBSTR)*2;          // 63488
    const int IX_SMEM  = (2*128*IXASTR + 2*80*IXBSTR)*2;        // 88576
    cudaFuncSetAttribute(k_lin_mma,   cudaFuncAttributeMaxDynamicSharedMemorySize, LIN_SMEM);
    cudaFuncSetAttribute(k_dfty_mma,  cudaFuncAttributeMaxDynamicSharedMemorySize, DFT_SMEM);
    cudaFuncSetAttribute(k_fc1_mma,   cudaFuncAttributeMaxDynamicSharedMemorySize, FC1_SMEM);
    cudaFuncSetAttribute(k_heads_mma, cudaFuncAttributeMaxDynamicSharedMemorySize, HED_SMEM);
    cudaFuncSetAttribute(k_dftx_mma,  cudaFuncAttributeMaxDynamicSharedMemorySize, DX_SMEM);
    cudaFuncSetAttribute(k_idftx_mma, cudaFuncAttributeMaxDynamicSharedMemorySize, IX_SMEM);

    k_packtw <<<48,256>>>();
    k_packtxf<<<512,96>>>();
    k_packtxi<<<80,512>>>();
    k_fc0<<<dim3(NP,NB),256>>>(x,fc0_w,fc0_b);
    for(int l=0;l<5;l++){
        int pp=l&1;
        k_dfty_mma <<<512,256,DFT_SMEM>>>(pp);
        k_dftx_mma <<<40,256,DX_SMEM>>>();
        k_mix  <<<dim3(KXN,5),1024>>>(sw1,sw2,l);
        k_idftx_mma<<<dim3(40,4),256,IX_SMEM>>>();
        k_lin_mma<<<dim3(512,1,NB),256,LIN_SMEM>>>(pp,w_w,w_b,l,(l<4)?1:0);
    }
    k_fc1_mma  <<<960,256,FC1_SMEM>>>(fc1_w,fc1_b);
    k_heads_mma<<<900,256,HED_SMEM>>>(h1w,h1b,h2w,h2b,out);
}